// round 13
// baseline (speedup 1.0000x reference)
#include <cuda_runtime.h>
#include <cuda_bf16.h>
#include <cuda_fp16.h>
#include <math.h>
#include <stdint.h>

#define BN_ 8
#define C_ 256
#define L_ 4096
#define BL_ (BN_*L_)
#define NCH 128
#define CHK 32
#define POS 32

// ---------------- scratch (device globals) -----------------------------------
__device__ __nv_bfloat16 g_ah[BL_*C_], g_al[BL_*C_];  // activation hi/lo
__device__ float   g_u  [BL_*C_];
__device__ float   g_z  [BL_*C_];
__device__ __half2 g_dtu[2][(size_t)BL_*C_];
__device__ float   g_bc [2][BL_*8];
__device__ float   g_cs [2][BN_*NCH*C_*8];
__device__ float   g_h0 [2][BN_*NCH*C_*4];
__device__ __nv_bfloat16 g_wih[512*256], g_wil[512*256];
__device__ __nv_bfloat16 g_woh[256*256], g_wol[256*256];

// ---------------- helpers -----------------------------------------------------
__device__ __forceinline__ float siluf(float x) { return x / (1.f + __expf(-x)); }

__device__ __forceinline__ uint32_t smem_u32(const void* p) {
    uint32_t a;
    asm("{ .reg .u64 t; cvta.to.shared.u64 t, %1; cvt.u32.u64 %0, t; }" : "=r"(a) : "l"(p));
    return a;
}

__device__ __forceinline__ void mma16816(float* c, const uint32_t* a, const uint32_t* b) {
    asm volatile(
        "mma.sync.aligned.m16n8k16.row.col.f32.bf16.bf16.f32 "
        "{%0,%1,%2,%3}, {%4,%5,%6,%7}, {%8,%9}, {%0,%1,%2,%3};"
        : "+f"(c[0]), "+f"(c[1]), "+f"(c[2]), "+f"(c[3])
        : "r"(a[0]), "r"(a[1]), "r"(a[2]), "r"(a[3]), "r"(b[0]), "r"(b[1]));
}

__device__ __forceinline__ void ldsm4(uint32_t* r, uint32_t addr) {
    asm volatile("ldmatrix.sync.aligned.m8n8.x4.shared.b16 {%0,%1,%2,%3}, [%4];"
        : "=r"(r[0]), "=r"(r[1]), "=r"(r[2]), "=r"(r[3]) : "r"(addr));
}

__device__ __forceinline__ void cpa16(uint32_t dst, const void* src) {
    asm volatile("cp.async.ca.shared.global [%0], [%1], 16;" :: "r"(dst), "l"(src));
}

__device__ __forceinline__ float dot4(float4 a, float4 b) {
    return fmaf(a.x, b.x, fmaf(a.y, b.y, fmaf(a.z, b.z, a.w * b.w)));
}

// ---------------- K0: weight pre-split ------------------------------------------
__global__ void wprep_kernel(const float* __restrict__ Wi, const float* __restrict__ Wo) {
    int i = blockIdx.x * 256 + threadIdx.x;
    if (i < 512 * 256) {
        float v = Wi[i];
        __nv_bfloat16 h = __float2bfloat16(v);
        g_wih[i] = h;
        g_wil[i] = __float2bfloat16(v - __bfloat162float(h));
    } else {
        int j = i - 512 * 256;
        float v = Wo[j];
        __nv_bfloat16 h = __float2bfloat16(v);
        g_woh[j] = h;
        g_wol[j] = __float2bfloat16(v - __bfloat162float(h));
    }
}

// ---------------- K1: tiled transpose + LayerNorm -> bf16 hi/lo ----------------
__global__ void ln_kernel(const float* __restrict__ x,
                          const float* __restrict__ wgt,
                          const float* __restrict__ bia) {
    __shared__ float s[C_][33];
    __shared__ float smu[32], srs[32];
    int b = blockIdx.x >> 7;
    int l0 = (blockIdx.x & 127) * 32;
    int tid = threadIdx.x, w = tid >> 5, ln = tid & 31;

    for (int c = w; c < C_; c += 8)
        s[c][ln] = x[((size_t)b * C_ + c) * L_ + l0 + ln];
    __syncthreads();

    #pragma unroll
    for (int j = 0; j < 4; j++) {
        int l = w * 4 + j;
        float sm = 0.f, sq = 0.f;
        #pragma unroll
        for (int i = 0; i < 8; i++) {
            float v = s[ln + 32 * i][l];
            sm += v; sq += v * v;
        }
        #pragma unroll
        for (int o = 16; o; o >>= 1) {
            sm += __shfl_down_sync(0xffffffffu, sm, o);
            sq += __shfl_down_sync(0xffffffffu, sq, o);
        }
        if (ln == 0) {
            float mu = sm * (1.f / C_);
            float var = sq * (1.f / C_) - mu * mu;
            smu[l] = mu; srs[l] = rsqrtf(var + 1e-5f);
        }
    }
    __syncthreads();

    int c = tid;
    float wv = wgt[c], bv = bia[c];
    for (int l = 0; l < 32; l++) {
        float v = (s[c][l] - smu[l]) * srs[l] * wv + bv;
        __nv_bfloat16 h = __float2bfloat16(v);
        size_t o = ((size_t)b * L_ + l0 + l) * C_ + c;
        g_ah[o] = h;
        g_al[o] = __float2bfloat16(v - __bfloat162float(h));
    }
}

// ---------------- K2: double-buffered cp.async split-bf16 HMMA GEMM ------------
#define SR 72
#define TILE_ELEM (128 * SR)
#define BUF_BYTES (4 * TILE_ELEM * 2)      // 73728
__global__ void __launch_bounds__(256, 1) gemm_hmma(
    const __nv_bfloat16* __restrict__ Ah, const __nv_bfloat16* __restrict__ Al,
    const __nv_bfloat16* __restrict__ Wh, const __nv_bfloat16* __restrict__ Wl,
    float* __restrict__ out0, float* __restrict__ out1,
    const float* __restrict__ xres, int mode) {
    extern __shared__ __nv_bfloat16 sm[];
    uint32_t sbase = smem_u32(sm);

    int tid = threadIdx.x, wid = tid >> 5, lid = tid & 31;
    int g = lid >> 2, t = lid & 3;
    int warp_m = wid & 1, warp_n = wid >> 1;
    int n0 = blockIdx.x * 128, m0 = blockIdx.y * 128;

    float acc[4][4][4] = {};

    int frow = tid >> 1;
    int fkh = (tid & 1) * 32;
    const __nv_bfloat16* srcs[4];
    srcs[0] = Ah + (size_t)(m0 + frow) * 256 + fkh;
    srcs[1] = Al + (size_t)(m0 + frow) * 256 + fkh;
    srcs[2] = Wh + (size_t)(n0 + frow) * 256 + fkh;
    srcs[3] = Wl + (size_t)(n0 + frow) * 256 + fkh;
    uint32_t fill_dst = sbase + (frow * SR + fkh) * 2;

    uint32_t aoff = ((warp_m * 64 + (lid & 15)) * SR + (lid >> 4) * 8) * 2;
    int bn = (lid & 7) + ((lid >> 4) << 3);
    uint32_t boff = ((warp_n * 32 + bn) * SR + ((lid >> 3) & 1) * 8) * 2;

    #pragma unroll
    for (int p = 0; p < 2; p++) {
        uint32_t db = fill_dst + p * BUF_BYTES;
        #pragma unroll
        for (int tno = 0; tno < 4; tno++)
            #pragma unroll
            for (int j = 0; j < 4; j++)
                cpa16(db + tno * (TILE_ELEM * 2) + j * 16, srcs[tno] + p * 64 + j * 8);
        asm volatile("cp.async.commit_group;" ::: "memory");
    }

    #pragma unroll
    for (int kc = 0; kc < 4; kc++) {
        if (kc < 3) asm volatile("cp.async.wait_group 1;" ::: "memory");
        else        asm volatile("cp.async.wait_group 0;" ::: "memory");
        __syncthreads();

        uint32_t bb = sbase + (kc & 1) * BUF_BYTES;
        uint32_t sAh_b = bb, sAl_b = bb + TILE_ELEM * 2;
        uint32_t sBh_b = bb + TILE_ELEM * 4, sBl_b = bb + TILE_ELEM * 6;

        #pragma unroll
        for (int ks = 0; ks < 4; ks++) {
            uint32_t bh[2][4], bl[2][4];
            ldsm4(bh[0], sBh_b + boff + ks * 32);
            ldsm4(bh[1], sBh_b + boff + 16 * SR * 2 + ks * 32);
            ldsm4(bl[0], sBl_b + boff + ks * 32);
            ldsm4(bl[1], sBl_b + boff + 16 * SR * 2 + ks * 32);
            #pragma unroll
            for (int mi = 0; mi < 4; mi++) {
                uint32_t ah[4], al[4];
                ldsm4(ah, sAh_b + aoff + mi * 16 * SR * 2 + ks * 32);
                ldsm4(al, sAl_b + aoff + mi * 16 * SR * 2 + ks * 32);
                #pragma unroll
                for (int ni = 0; ni < 4; ni++) {
                    const uint32_t* bph = &bh[ni >> 1][(ni & 1) * 2];
                    const uint32_t* bpl = &bl[ni >> 1][(ni & 1) * 2];
                    mma16816(acc[mi][ni], ah, bph);
                    mma16816(acc[mi][ni], ah, bpl);
                    mma16816(acc[mi][ni], al, bph);
                }
            }
        }
        __syncthreads();
        if (kc < 2) {
            uint32_t db = fill_dst + (kc & 1) * BUF_BYTES;
            #pragma unroll
            for (int tno = 0; tno < 4; tno++)
                #pragma unroll
                for (int j = 0; j < 4; j++)
                    cpa16(db + tno * (TILE_ELEM * 2) + j * 16, srcs[tno] + (kc + 2) * 64 + j * 8);
            asm volatile("cp.async.commit_group;" ::: "memory");
        }
    }

    if (mode == 0) {
        float* dst = (n0 < 256) ? out0 : out1;
        int nb = n0 & 255;
        #pragma unroll
        for (int mi = 0; mi < 4; mi++) {
            int r = m0 + warp_m * 64 + mi * 16 + g;
            #pragma unroll
            for (int ni = 0; ni < 4; ni++) {
                int n = nb + warp_n * 32 + ni * 8 + t * 2;
                *(float2*)&dst[(size_t)r * 256 + n] = make_float2(acc[mi][ni][0], acc[mi][ni][1]);
                *(float2*)&dst[(size_t)(r + 8) * 256 + n] = make_float2(acc[mi][ni][2], acc[mi][ni][3]);
            }
        }
    } else {
        int bb2 = m0 >> 12, l0 = m0 & 4095;
        #pragma unroll
        for (int mi = 0; mi < 4; mi++) {
            int l = l0 + warp_m * 64 + mi * 16 + g;
            #pragma unroll
            for (int ni = 0; ni < 4; ni++) {
                int ch = n0 + warp_n * 32 + ni * 8 + t * 2;
                size_t o0 = ((size_t)bb2 * C_ + ch) * L_ + l;
                out0[o0]          = acc[mi][ni][0] + xres[o0];
                out0[o0 + L_]     = acc[mi][ni][1] + xres[o0 + L_];
                out0[o0 + 8]      = acc[mi][ni][2] + xres[o0 + 8];
                out0[o0 + L_ + 8] = acc[mi][ni][3] + xres[o0 + L_ + 8];
            }
        }
    }
}

// ---------------- K3: conv + silu + x_proj + dt_proj + scan-phase1 -------------
// Conflict-free vectorized LDS: plain layout, 4-word lane stride for float4 loads.
__global__ void __launch_bounds__(256, 2) convscan_kernel(
    const float* __restrict__ cw0, const float* __restrict__ cb0,
    const float* __restrict__ xp0, const float* __restrict__ dw0, const float* __restrict__ db0,
    const float* __restrict__ Alog0,
    const float* __restrict__ cw1, const float* __restrict__ cb1,
    const float* __restrict__ xp1, const float* __restrict__ dw1, const float* __restrict__ db1,
    const float* __restrict__ Alog1) {
    extern __shared__ float sh[];
    float* sxc  = sh;                  // 32 x 256 (plain)
    float* sxp  = sxc + 32 * C_;       // 24 x 256 (plain)
    float* sdw4 = sxp + 24 * C_;       // float4-contig: [q][c] -> words q*1024 + c*4 + j
    float* sdbl = sdw4 + 16 * C_;      // 32 x 24

    int chk = blockIdx.x;
    int b = blockIdx.y >> 1, dir = blockIdx.y & 1;
    const float* cw = dir ? cw1 : cw0;
    const float* cb = dir ? cb1 : cb0;
    const float* xp = dir ? xp1 : xp0;
    const float* dw = dir ? dw1 : dw0;
    const float* db = dir ? db1 : db0;
    const float* Alog = dir ? Alog1 : Alog0;
    int tid = threadIdx.x;
    int q0 = chk * POS;

    for (int i = tid; i < 24 * C_; i += 256) sxp[i] = xp[i];
    for (int i = tid; i < 16 * C_; i += 256) {
        int c = i >> 4, r = i & 15;
        sdw4[(r >> 2) * 1024 + c * 4 + (r & 3)] = dw[i];
    }

    {   // conv + silu: rolling 4-register window over g_u
        int c = tid;
        float w0 = cw[c], w1 = cw[C_ + c], w2 = cw[2 * C_ + c], w3 = cw[3 * C_ + c];
        float cbv = cb[c];
        float u0 = 0.f, u1 = 0.f, u2 = 0.f;
        #pragma unroll
        for (int j = 0; j < 3; j++) {
            int q = q0 - 3 + j;
            float v = 0.f;
            if (q >= 0) {
                int phys = dir ? (L_ - 1 - q) : q;
                v = g_u[(size_t)(b * L_ + phys) * C_ + c];
            }
            if (j == 0) u0 = v; else if (j == 1) u1 = v; else u2 = v;
        }
        #pragma unroll 4
        for (int tp = 0; tp < POS; tp++) {
            int q = q0 + tp;
            int phys = dir ? (L_ - 1 - q) : q;
            float u3 = g_u[(size_t)(b * L_ + phys) * C_ + c];
            float acc = cbv;
            acc = fmaf(w0, u0, acc);
            acc = fmaf(w1, u1, acc);
            acc = fmaf(w2, u2, acc);
            acc = fmaf(w3, u3, acc);
            sxc[tp * C_ + c] = siluf(acc);
            u0 = u1; u1 = u2; u2 = u3;
        }
    }
    __syncthreads();

    {   // x_dbl: lane ln owns channel quads [4ln,4ln+4) and [128+4ln,128+4ln+4)
        // float4 loads at 4-word lane stride -> conflict-free
        int w = tid >> 5, ln = tid & 31;
        int kq0 = 4 * ln, kq1 = 128 + 4 * ln;
        #pragma unroll 1
        for (int ti = 0; ti < 4; ti++) {
            int tp = w * 4 + ti;
            float4 xa = *(const float4*)&sxc[tp * C_ + kq0];
            float4 xb = *(const float4*)&sxc[tp * C_ + kq1];
            #pragma unroll 1
            for (int b3 = 0; b3 < 3; b3++) {
                float accs[8];
                #pragma unroll
                for (int o = 0; o < 8; o++) {
                    int o2 = b3 * 8 + o;
                    float4 pa = *(const float4*)&sxp[o2 * C_ + kq0];
                    float4 pb = *(const float4*)&sxp[o2 * C_ + kq1];
                    accs[o] = dot4(xa, pa) + dot4(xb, pb);
                }
                #pragma unroll
                for (int of = 16; of; of >>= 1)
                    #pragma unroll
                    for (int o = 0; o < 8; o++)
                        accs[o] += __shfl_down_sync(0xffffffffu, accs[o], of);
                if (ln == 0) {
                    #pragma unroll
                    for (int o = 0; o < 8; o++) sdbl[tp * 24 + b3 * 8 + o] = accs[o];
                }
            }
        }
    }
    __syncthreads();

    if (tid < POS * 8) {
        int pos = tid >> 3, v = tid & 7;
        g_bc[dir][(size_t)(b * L_ + q0 + pos) * 8 + v] = sdbl[pos * 24 + 16 + v];
    }

    {   // dt_proj + softplus + chunk summary; weights in registers
        int c = tid;
        float dbv = db[c];
        float4 wq0 = *(const float4*)&sdw4[0 * 1024 + c * 4];
        float4 wq1 = *(const float4*)&sdw4[1 * 1024 + c * 4];
        float4 wq2 = *(const float4*)&sdw4[2 * 1024 + c * 4];
        float4 wq3 = *(const float4*)&sdw4[3 * 1024 + c * 4];
        float Av[4];
        #pragma unroll
        for (int n = 0; n < 4; n++) Av[n] = -__expf(Alog[c * 4 + n]);
        float h[4] = {0, 0, 0, 0}, aP[4] = {1, 1, 1, 1};
        #pragma unroll 1
        for (int pos = 0; pos < POS; pos++) {
            float4 d0 = *(const float4*)&sdbl[pos * 24];          // broadcast
            float4 d1 = *(const float4*)&sdbl[pos * 24 + 4];
            float4 d2 = *(const float4*)&sdbl[pos * 24 + 8];
            float4 d3 = *(const float4*)&sdbl[pos * 24 + 12];
            float4 bcv = *(const float4*)&sdbl[pos * 24 + 16];
            float val = dbv + dot4(d0, wq0) + dot4(d1, wq1) + dot4(d2, wq2) + dot4(d3, wq3);
            float dtv = (val > 20.f) ? val : log1pf(__expf(val));
            float uu = sxc[pos * C_ + c];
            __half2 p = __floats2half2_rn(dtv, uu);
            g_dtu[dir][(size_t)(b * L_ + q0 + pos) * C_ + c] = p;
            float2 q = __half22float2(p);
            float du = q.x * q.y;
            float bcb[4] = {bcv.x, bcv.y, bcv.z, bcv.w};
            #pragma unroll
            for (int n = 0; n < 4; n++) {
                float a = __expf(q.x * Av[n]);
                h[n] = fmaf(a, h[n], du * bcb[n]);
                aP[n] *= a;
            }
        }
        float* cs = g_cs[dir] + ((size_t)(b * NCH + chk) * C_ + c) * 8;
        #pragma unroll
        for (int n = 0; n < 4; n++) { cs[n * 2] = aP[n]; cs[n * 2 + 1] = h[n]; }
    }
}

// ---------------- K4: scan phase 2 ---------------------------------------------
__global__ void scan2_kernel() {
    int tg = blockIdx.x * 256 + threadIdx.x;
    int bd = tg >> 10;
    int cn = tg & 1023;
    int b = bd >> 1, dir = bd & 1;
    const float2* cs = (const float2*)(g_cs[dir] + (size_t)b * NCH * C_ * 8) + cn;
    float* h0 = g_h0[dir] + (size_t)b * NCH * C_ * 4 + cn;
    float B = 0.f;
    #pragma unroll 8
    for (int ch = 0; ch < NCH; ch++) {
        float2 v = cs[(size_t)ch * 1024];
        h0[(size_t)ch * 1024] = B;
        B = fmaf(v.x, B, v.y);
    }
}

// ---------------- K5: fused replay(f+b) + combine + silu(z) + LN ----------------
__global__ void scan3_fused_kernel(
    const float* __restrict__ Alog0, const float* __restrict__ Alog1,
    const float* __restrict__ D0, const float* __restrict__ D1,
    const float* __restrict__ nw, const float* __restrict__ nb) {
    __shared__ float sbcf[CHK * 8], sbcb[CHK * 8];
    __shared__ float ysm[CHK * C_];
    __shared__ float smu[CHK], srs[CHK];

    int ch = blockIdx.x;
    int b  = blockIdx.y;
    int c  = threadIdx.x;
    int chb = NCH - 1 - ch;
    int l0 = ch * CHK;

    {
        const float* gf = g_bc[0] + (size_t)(b * L_ + ch * CHK) * 8;
        const float* gb = g_bc[1] + (size_t)(b * L_ + chb * CHK) * 8;
        if (c < CHK * 8) { sbcf[c] = gf[c]; sbcb[c] = gb[c]; }
    }
    __syncthreads();

    // forward replay
    {
        float Av[4];
        #pragma unroll
        for (int n = 0; n < 4; n++) Av[n] = -__expf(Alog0[c * 4 + n]);
        float Dv = D0[c];
        const float* h0p = g_h0[0] + ((size_t)(b * NCH + ch) * C_ + c) * 4;
        float h[4];
        #pragma unroll
        for (int n = 0; n < 4; n++) h[n] = h0p[n];
        const __half2* dtu = &g_dtu[0][(size_t)(b * L_ + l0) * C_ + c];
        #pragma unroll 4
        for (int t = 0; t < CHK; t++) {
            float2 v = __half22float2(dtu[(size_t)t * C_]);
            float du = v.x * v.y;
            float y = v.y * Dv;
            #pragma unroll
            for (int n = 0; n < 4; n++) {
                float a = __expf(v.x * Av[n]);
                h[n] = fmaf(a, h[n], du * sbcf[t * 8 + n]);
                y = fmaf(h[n], sbcf[t * 8 + 4 + n], y);
            }
            ysm[t * C_ + c] = y;
        }
    }
    // backward replay
    {
        float Av[4];
        #pragma unroll
        for (int n = 0; n < 4; n++) Av[n] = -__expf(Alog1[c * 4 + n]);
        float Dv = D1[c];
        const float* h0p = g_h0[1] + ((size_t)(b * NCH + chb) * C_ + c) * 4;
        float h[4];
        #pragma unroll
        for (int n = 0; n < 4; n++) h[n] = h0p[n];
        const __half2* dtu = &g_dtu[1][(size_t)(b * L_ + chb * CHK) * C_ + c];
        #pragma unroll 4
        for (int tb = 0; tb < CHK; tb++) {
            float2 v = __half22float2(dtu[(size_t)tb * C_]);
            float du = v.x * v.y;
            float y = v.y * Dv;
            #pragma unroll
            for (int n = 0; n < 4; n++) {
                float a = __expf(v.x * Av[n]);
                h[n] = fmaf(a, h[n], du * sbcb[tb * 8 + n]);
                y = fmaf(h[n], sbcb[tb * 8 + 4 + n], y);
            }
            ysm[(CHK - 1 - tb) * C_ + c] += y;
        }
    }
    // z-gate
    {
        const float* zp = &g_z[(size_t)(b * L_ + l0) * C_ + c];
        #pragma unroll 4
        for (int t = 0; t < CHK; t++) {
            float z = zp[(size_t)t * C_];
            ysm[t * C_ + c] = 0.5f * ysm[t * C_ + c] * siluf(z);
        }
    }
    __syncthreads();
    // LN stats
    {
        int w = c >> 5, ln = c & 31;
        #pragma unroll
        for (int j = 0; j < 4; j++) {
            int t = w * 4 + j;
            float sm = 0.f, sq = 0.f;
            #pragma unroll
            for (int i = 0; i < 8; i++) {
                float v = ysm[t * C_ + ln + 32 * i];
                sm += v; sq += v * v;
            }
            #pragma unroll
            for (int o = 16; o; o >>= 1) {
                sm += __shfl_down_sync(0xffffffffu, sm, o);
                sq += __shfl_down_sync(0xffffffffu, sq, o);
            }
            if (ln == 0) {
                float mu = sm * (1.f / C_);
                float var = sq * (1.f / C_) - mu * mu;
                smu[t] = mu; srs[t] = rsqrtf(var + 1e-5f);
            }
        }
    }
    __syncthreads();
    {
        float wv = nw[c], bv = nb[c];
        #pragma unroll 4
        for (int t = 0; t < CHK; t++) {
            float v = (ysm[t * C_ + c] - smu[t]) * srs[t] * wv + bv;
            __nv_bfloat16 hh = __float2bfloat16(v);
            size_t o = (size_t)(b * L_ + l0 + t) * C_ + c;
            g_ah[o] = hh;
            g_al[o] = __float2bfloat16(v - __bfloat162float(hh));
        }
    }
}

// ---------------- launch ---------------------------------------------------------
extern "C" void kernel_launch(void* const* d_in, const int* in_sizes, int n_in,
                              void* d_out, int out_size) {
    const float* x        = (const float*)d_in[0];
    const float* ln_w     = (const float*)d_in[1];
    const float* ln_b     = (const float*)d_in[2];
    const float* in_proj  = (const float*)d_in[3];
    const float* cw_f     = (const float*)d_in[4];
    const float* cb_f     = (const float*)d_in[5];
    const float* xp_f     = (const float*)d_in[6];
    const float* dw_f     = (const float*)d_in[7];
    const float* db_f     = (const float*)d_in[8];
    const float* Alog_f   = (const float*)d_in[9];
    const float* D_f      = (const float*)d_in[10];
    const float* cw_b     = (const float*)d_in[11];
    const float* cb_b     = (const float*)d_in[12];
    const float* xp_b     = (const float*)d_in[13];
    const float* dw_b     = (const float*)d_in[14];
    const float* db_b     = (const float*)d_in[15];
    const float* Alog_b   = (const float*)d_in[16];
    const float* D_b      = (const float*)d_in[17];
    const float* nrm_w    = (const float*)d_in[18];
    const float* nrm_b    = (const float*)d_in[19];
    const float* out_proj = (const float*)d_in[20];
    float* out = (float*)d_out;

    float* gu;  cudaGetSymbolAddress((void**)&gu,  g_u);
    float* gz;  cudaGetSymbolAddress((void**)&gz,  g_z);
    __nv_bfloat16 *gah, *gal, *wih, *wil, *woh, *wol;
    cudaGetSymbolAddress((void**)&gah, g_ah);
    cudaGetSymbolAddress((void**)&gal, g_al);
    cudaGetSymbolAddress((void**)&wih, g_wih);
    cudaGetSymbolAddress((void**)&wil, g_wil);
    cudaGetSymbolAddress((void**)&woh, g_woh);
    cudaGetSymbolAddress((void**)&wol, g_wol);

    const int gemm_smem = 2 * BUF_BYTES;   // 147456 B
    cudaFuncSetAttribute(gemm_hmma, cudaFuncAttributeMaxDynamicSharedMemorySize, gemm_smem);
    const int conv_smem = (32 * C_ + 24 * C_ + 16 * C_ + 32 * 24) * 4;   // ~75 KB
    cudaFuncSetAttribute(convscan_kernel, cudaFuncAttributeMaxDynamicSharedMemorySize, conv_smem);

    wprep_kernel<<<768, 256>>>(in_proj, out_proj);
    ln_kernel<<<BN_ * 128, 256>>>(x, ln_w, ln_b);
    gemm_hmma<<<dim3(4, BL_ / 128), 256, gemm_smem>>>(gah, gal, wih, wil, gu, gz, nullptr, 0);
    convscan_kernel<<<dim3(NCH, BN_ * 2), 256, conv_smem>>>(
        cw_f, cb_f, xp_f, dw_f, db_f, Alog_f,
        cw_b, cb_b, xp_b, dw_b, db_b, Alog_b);
    scan2_kernel<<<64, 256>>>();
    scan3_fused_kernel<<<dim3(NCH, BN_), 256>>>(Alog_f, Alog_b, D_f, D_b, nrm_w, nrm_b);
    gemm_hmma<<<dim3(2, BL_ / 128), 256, gemm_smem>>>(gah, gal, woh, wol, out, nullptr, x, 1);
}

// round 14
// speedup vs baseline: 1.1322x; 1.1322x over previous
#include <cuda_runtime.h>
#include <cuda_bf16.h>
#include <cuda_fp16.h>
#include <math.h>
#include <stdint.h>

#define BN_ 8
#define C_ 256
#define L_ 4096
#define BL_ (BN_*L_)
#define NCH 128
#define CHK 32
#define POS 32

// ---------------- scratch (device globals) -----------------------------------
__device__ __nv_bfloat16 g_ah[BL_*C_], g_al[BL_*C_];  // activation hi/lo
__device__ float   g_u  [BL_*C_];
__device__ float   g_z  [BL_*C_];
__device__ __half2 g_dtu[2][(size_t)BL_*C_];
__device__ float   g_bc [2][BL_*8];
__device__ float   g_cs [2][BN_*NCH*C_*8];
__device__ float   g_h0 [2][BN_*NCH*C_*4];
__device__ __nv_bfloat16 g_wih[512*256], g_wil[512*256];
__device__ __nv_bfloat16 g_woh[256*256], g_wol[256*256];

// ---------------- helpers -----------------------------------------------------
__device__ __forceinline__ float siluf(float x) { return x / (1.f + __expf(-x)); }

__device__ __forceinline__ uint32_t smem_u32(const void* p) {
    uint32_t a;
    asm("{ .reg .u64 t; cvta.to.shared.u64 t, %1; cvt.u32.u64 %0, t; }" : "=r"(a) : "l"(p));
    return a;
}

__device__ __forceinline__ void mma16816(float* c, const uint32_t* a, const uint32_t* b) {
    asm volatile(
        "mma.sync.aligned.m16n8k16.row.col.f32.bf16.bf16.f32 "
        "{%0,%1,%2,%3}, {%4,%5,%6,%7}, {%8,%9}, {%0,%1,%2,%3};"
        : "+f"(c[0]), "+f"(c[1]), "+f"(c[2]), "+f"(c[3])
        : "r"(a[0]), "r"(a[1]), "r"(a[2]), "r"(a[3]), "r"(b[0]), "r"(b[1]));
}

__device__ __forceinline__ void ldsm4(uint32_t* r, uint32_t addr) {
    asm volatile("ldmatrix.sync.aligned.m8n8.x4.shared.b16 {%0,%1,%2,%3}, [%4];"
        : "=r"(r[0]), "=r"(r[1]), "=r"(r[2]), "=r"(r[3]) : "r"(addr));
}

__device__ __forceinline__ void cpa16(uint32_t dst, const void* src) {
    asm volatile("cp.async.ca.shared.global [%0], [%1], 16;" :: "r"(dst), "l"(src));
}

__device__ __forceinline__ float dot4(float4 a, float4 b) {
    return fmaf(a.x, b.x, fmaf(a.y, b.y, fmaf(a.z, b.z, a.w * b.w)));
}

// ---------------- K0: weight pre-split ------------------------------------------
__global__ void wprep_kernel(const float* __restrict__ Wi, const float* __restrict__ Wo) {
    int i = blockIdx.x * 256 + threadIdx.x;
    if (i < 512 * 256) {
        float v = Wi[i];
        __nv_bfloat16 h = __float2bfloat16(v);
        g_wih[i] = h;
        g_wil[i] = __float2bfloat16(v - __bfloat162float(h));
    } else {
        int j = i - 512 * 256;
        float v = Wo[j];
        __nv_bfloat16 h = __float2bfloat16(v);
        g_woh[j] = h;
        g_wol[j] = __float2bfloat16(v - __bfloat162float(h));
    }
}

// ---------------- K1: tiled transpose + LayerNorm -> bf16 hi/lo ----------------
__global__ void ln_kernel(const float* __restrict__ x,
                          const float* __restrict__ wgt,
                          const float* __restrict__ bia) {
    __shared__ float s[C_][33];
    __shared__ float smu[32], srs[32];
    int b = blockIdx.x >> 7;
    int l0 = (blockIdx.x & 127) * 32;
    int tid = threadIdx.x, w = tid >> 5, ln = tid & 31;

    for (int c = w; c < C_; c += 8)
        s[c][ln] = x[((size_t)b * C_ + c) * L_ + l0 + ln];
    __syncthreads();

    #pragma unroll
    for (int j = 0; j < 4; j++) {
        int l = w * 4 + j;
        float sm = 0.f, sq = 0.f;
        #pragma unroll
        for (int i = 0; i < 8; i++) {
            float v = s[ln + 32 * i][l];
            sm += v; sq += v * v;
        }
        #pragma unroll
        for (int o = 16; o; o >>= 1) {
            sm += __shfl_down_sync(0xffffffffu, sm, o);
            sq += __shfl_down_sync(0xffffffffu, sq, o);
        }
        if (ln == 0) {
            float mu = sm * (1.f / C_);
            float var = sq * (1.f / C_) - mu * mu;
            smu[l] = mu; srs[l] = rsqrtf(var + 1e-5f);
        }
    }
    __syncthreads();

    int c = tid;
    float wv = wgt[c], bv = bia[c];
    for (int l = 0; l < 32; l++) {
        float v = (s[c][l] - smu[l]) * srs[l] * wv + bv;
        __nv_bfloat16 h = __float2bfloat16(v);
        size_t o = ((size_t)b * L_ + l0 + l) * C_ + c;
        g_ah[o] = h;
        g_al[o] = __float2bfloat16(v - __bfloat162float(h));
    }
}

// ---------------- K2: double-buffered cp.async split-bf16 HMMA GEMM ------------
#define SR 72
#define TILE_ELEM (128 * SR)
#define BUF_BYTES (4 * TILE_ELEM * 2)      // 73728
__global__ void __launch_bounds__(256, 1) gemm_hmma(
    const __nv_bfloat16* __restrict__ Ah, const __nv_bfloat16* __restrict__ Al,
    const __nv_bfloat16* __restrict__ Wh, const __nv_bfloat16* __restrict__ Wl,
    float* __restrict__ out0, float* __restrict__ out1,
    const float* __restrict__ xres, int mode) {
    extern __shared__ __nv_bfloat16 sm[];
    uint32_t sbase = smem_u32(sm);

    int tid = threadIdx.x, wid = tid >> 5, lid = tid & 31;
    int g = lid >> 2, t = lid & 3;
    int warp_m = wid & 1, warp_n = wid >> 1;
    int n0 = blockIdx.x * 128, m0 = blockIdx.y * 128;

    float acc[4][4][4] = {};

    int frow = tid >> 1;
    int fkh = (tid & 1) * 32;
    const __nv_bfloat16* srcs[4];
    srcs[0] = Ah + (size_t)(m0 + frow) * 256 + fkh;
    srcs[1] = Al + (size_t)(m0 + frow) * 256 + fkh;
    srcs[2] = Wh + (size_t)(n0 + frow) * 256 + fkh;
    srcs[3] = Wl + (size_t)(n0 + frow) * 256 + fkh;
    uint32_t fill_dst = sbase + (frow * SR + fkh) * 2;

    uint32_t aoff = ((warp_m * 64 + (lid & 15)) * SR + (lid >> 4) * 8) * 2;
    int bn = (lid & 7) + ((lid >> 4) << 3);
    uint32_t boff = ((warp_n * 32 + bn) * SR + ((lid >> 3) & 1) * 8) * 2;

    #pragma unroll
    for (int p = 0; p < 2; p++) {
        uint32_t db = fill_dst + p * BUF_BYTES;
        #pragma unroll
        for (int tno = 0; tno < 4; tno++)
            #pragma unroll
            for (int j = 0; j < 4; j++)
                cpa16(db + tno * (TILE_ELEM * 2) + j * 16, srcs[tno] + p * 64 + j * 8);
        asm volatile("cp.async.commit_group;" ::: "memory");
    }

    #pragma unroll
    for (int kc = 0; kc < 4; kc++) {
        if (kc < 3) asm volatile("cp.async.wait_group 1;" ::: "memory");
        else        asm volatile("cp.async.wait_group 0;" ::: "memory");
        __syncthreads();

        uint32_t bb = sbase + (kc & 1) * BUF_BYTES;
        uint32_t sAh_b = bb, sAl_b = bb + TILE_ELEM * 2;
        uint32_t sBh_b = bb + TILE_ELEM * 4, sBl_b = bb + TILE_ELEM * 6;

        #pragma unroll
        for (int ks = 0; ks < 4; ks++) {
            uint32_t bh[2][4], bl[2][4];
            ldsm4(bh[0], sBh_b + boff + ks * 32);
            ldsm4(bh[1], sBh_b + boff + 16 * SR * 2 + ks * 32);
            ldsm4(bl[0], sBl_b + boff + ks * 32);
            ldsm4(bl[1], sBl_b + boff + 16 * SR * 2 + ks * 32);
            #pragma unroll
            for (int mi = 0; mi < 4; mi++) {
                uint32_t ah[4], al[4];
                ldsm4(ah, sAh_b + aoff + mi * 16 * SR * 2 + ks * 32);
                ldsm4(al, sAl_b + aoff + mi * 16 * SR * 2 + ks * 32);
                #pragma unroll
                for (int ni = 0; ni < 4; ni++) {
                    const uint32_t* bph = &bh[ni >> 1][(ni & 1) * 2];
                    const uint32_t* bpl = &bl[ni >> 1][(ni & 1) * 2];
                    mma16816(acc[mi][ni], ah, bph);
                    mma16816(acc[mi][ni], ah, bpl);
                    mma16816(acc[mi][ni], al, bph);
                }
            }
        }
        __syncthreads();
        if (kc < 2) {
            uint32_t db = fill_dst + (kc & 1) * BUF_BYTES;
            #pragma unroll
            for (int tno = 0; tno < 4; tno++)
                #pragma unroll
                for (int j = 0; j < 4; j++)
                    cpa16(db + tno * (TILE_ELEM * 2) + j * 16, srcs[tno] + (kc + 2) * 64 + j * 8);
            asm volatile("cp.async.commit_group;" ::: "memory");
        }
    }

    if (mode == 0) {
        float* dst = (n0 < 256) ? out0 : out1;
        int nb = n0 & 255;
        #pragma unroll
        for (int mi = 0; mi < 4; mi++) {
            int r = m0 + warp_m * 64 + mi * 16 + g;
            #pragma unroll
            for (int ni = 0; ni < 4; ni++) {
                int n = nb + warp_n * 32 + ni * 8 + t * 2;
                *(float2*)&dst[(size_t)r * 256 + n] = make_float2(acc[mi][ni][0], acc[mi][ni][1]);
                *(float2*)&dst[(size_t)(r + 8) * 256 + n] = make_float2(acc[mi][ni][2], acc[mi][ni][3]);
            }
        }
    } else {
        int bb2 = m0 >> 12, l0 = m0 & 4095;
        #pragma unroll
        for (int mi = 0; mi < 4; mi++) {
            int l = l0 + warp_m * 64 + mi * 16 + g;
            #pragma unroll
            for (int ni = 0; ni < 4; ni++) {
                int ch = n0 + warp_n * 32 + ni * 8 + t * 2;
                size_t o0 = ((size_t)bb2 * C_ + ch) * L_ + l;
                out0[o0]          = acc[mi][ni][0] + xres[o0];
                out0[o0 + L_]     = acc[mi][ni][1] + xres[o0 + L_];
                out0[o0 + 8]      = acc[mi][ni][2] + xres[o0 + 8];
                out0[o0 + L_ + 8] = acc[mi][ni][3] + xres[o0 + L_ + 8];
            }
        }
    }
}

// ---------------- K3: conv + silu + x_proj + dt_proj + scan-phase1 -------------
// 3 CTAs/SM (launch_bounds), warp-owns-outputs x_dbl (sxp rows in registers).
__global__ void __launch_bounds__(256, 3) convscan_kernel(
    const float* __restrict__ cw0, const float* __restrict__ cb0,
    const float* __restrict__ xp0, const float* __restrict__ dw0, const float* __restrict__ db0,
    const float* __restrict__ Alog0,
    const float* __restrict__ cw1, const float* __restrict__ cb1,
    const float* __restrict__ xp1, const float* __restrict__ dw1, const float* __restrict__ db1,
    const float* __restrict__ Alog1) {
    extern __shared__ float sh[];
    float* sxc  = sh;                  // 32 x 256 (plain)
    float* sxp  = sxc + 32 * C_;       // 24 x 256 (plain)
    float* sdw4 = sxp + 24 * C_;       // [q][c] float4-contiguous
    float* sdbl = sdw4 + 16 * C_;      // 32 x 24

    int chk = blockIdx.x;
    int b = blockIdx.y >> 1, dir = blockIdx.y & 1;
    const float* cw = dir ? cw1 : cw0;
    const float* cb = dir ? cb1 : cb0;
    const float* xp = dir ? xp1 : xp0;
    const float* dw = dir ? dw1 : dw0;
    const float* db = dir ? db1 : db0;
    const float* Alog = dir ? Alog1 : Alog0;
    int tid = threadIdx.x;
    int q0 = chk * POS;

    for (int i = tid; i < 24 * C_; i += 256) sxp[i] = xp[i];
    for (int i = tid; i < 16 * C_; i += 256) {
        int c = i >> 4, r = i & 15;
        sdw4[(r >> 2) * 1024 + c * 4 + (r & 3)] = dw[i];
    }

    {   // conv + silu: rolling 4-register window over g_u
        int c = tid;
        float w0 = cw[c], w1 = cw[C_ + c], w2 = cw[2 * C_ + c], w3 = cw[3 * C_ + c];
        float cbv = cb[c];
        float u0 = 0.f, u1 = 0.f, u2 = 0.f;
        #pragma unroll
        for (int j = 0; j < 3; j++) {
            int q = q0 - 3 + j;
            float v = 0.f;
            if (q >= 0) {
                int phys = dir ? (L_ - 1 - q) : q;
                v = g_u[(size_t)(b * L_ + phys) * C_ + c];
            }
            if (j == 0) u0 = v; else if (j == 1) u1 = v; else u2 = v;
        }
        #pragma unroll 4
        for (int tp = 0; tp < POS; tp++) {
            int q = q0 + tp;
            int phys = dir ? (L_ - 1 - q) : q;
            float u3 = g_u[(size_t)(b * L_ + phys) * C_ + c];
            float acc = cbv;
            acc = fmaf(w0, u0, acc);
            acc = fmaf(w1, u1, acc);
            acc = fmaf(w2, u2, acc);
            acc = fmaf(w3, u3, acc);
            sxc[tp * C_ + c] = siluf(acc);
            u0 = u1; u1 = u2; u2 = u3;
        }
    }
    __syncthreads();

    {   // x_dbl: warp w owns outputs {3w,3w+1,3w+2} for ALL positions;
        // its 3 sxp rows live in registers. Lane ln holds k-quads
        // [4ln,4ln+4) and [128+4ln,128+4ln+4) — conflict-free float4 loads.
        int w = tid >> 5, ln = tid & 31;
        int kq0 = 4 * ln, kq1 = 128 + 4 * ln;
        float4 pa0 = *(const float4*)&sxp[(w * 3 + 0) * C_ + kq0];
        float4 pb0 = *(const float4*)&sxp[(w * 3 + 0) * C_ + kq1];
        float4 pa1 = *(const float4*)&sxp[(w * 3 + 1) * C_ + kq0];
        float4 pb1 = *(const float4*)&sxp[(w * 3 + 1) * C_ + kq1];
        float4 pa2 = *(const float4*)&sxp[(w * 3 + 2) * C_ + kq0];
        float4 pb2 = *(const float4*)&sxp[(w * 3 + 2) * C_ + kq1];
        #pragma unroll 2
        for (int tp = 0; tp < POS; tp++) {
            float4 xa = *(const float4*)&sxc[tp * C_ + kq0];
            float4 xb = *(const float4*)&sxc[tp * C_ + kq1];
            float a0 = dot4(xa, pa0) + dot4(xb, pb0);
            float a1 = dot4(xa, pa1) + dot4(xb, pb1);
            float a2 = dot4(xa, pa2) + dot4(xb, pb2);
            #pragma unroll
            for (int of = 16; of; of >>= 1) {
                a0 += __shfl_down_sync(0xffffffffu, a0, of);
                a1 += __shfl_down_sync(0xffffffffu, a1, of);
                a2 += __shfl_down_sync(0xffffffffu, a2, of);
            }
            if (ln == 0) {
                sdbl[tp * 24 + w * 3 + 0] = a0;
                sdbl[tp * 24 + w * 3 + 1] = a1;
                sdbl[tp * 24 + w * 3 + 2] = a2;
            }
        }
    }
    __syncthreads();

    if (tid < POS * 8) {
        int pos = tid >> 3, v = tid & 7;
        g_bc[dir][(size_t)(b * L_ + q0 + pos) * 8 + v] = sdbl[pos * 24 + 16 + v];
    }

    {   // dt_proj + softplus + chunk summary; weights in registers
        int c = tid;
        float dbv = db[c];
        float4 wq0 = *(const float4*)&sdw4[0 * 1024 + c * 4];
        float4 wq1 = *(const float4*)&sdw4[1 * 1024 + c * 4];
        float4 wq2 = *(const float4*)&sdw4[2 * 1024 + c * 4];
        float4 wq3 = *(const float4*)&sdw4[3 * 1024 + c * 4];
        float Av[4];
        #pragma unroll
        for (int n = 0; n < 4; n++) Av[n] = -__expf(Alog[c * 4 + n]);
        float h[4] = {0, 0, 0, 0}, aP[4] = {1, 1, 1, 1};
        #pragma unroll 1
        for (int pos = 0; pos < POS; pos++) {
            float4 d0 = *(const float4*)&sdbl[pos * 24];
            float4 d1 = *(const float4*)&sdbl[pos * 24 + 4];
            float4 d2 = *(const float4*)&sdbl[pos * 24 + 8];
            float4 d3 = *(const float4*)&sdbl[pos * 24 + 12];
            float4 bcv = *(const float4*)&sdbl[pos * 24 + 16];
            float val = dbv + dot4(d0, wq0) + dot4(d1, wq1) + dot4(d2, wq2) + dot4(d3, wq3);
            float dtv = (val > 20.f) ? val : log1pf(__expf(val));
            float uu = sxc[pos * C_ + c];
            __half2 p = __floats2half2_rn(dtv, uu);
            g_dtu[dir][(size_t)(b * L_ + q0 + pos) * C_ + c] = p;
            float2 q = __half22float2(p);
            float du = q.x * q.y;
            float bcb[4] = {bcv.x, bcv.y, bcv.z, bcv.w};
            #pragma unroll
            for (int n = 0; n < 4; n++) {
                float a = __expf(q.x * Av[n]);
                h[n] = fmaf(a, h[n], du * bcb[n]);
                aP[n] *= a;
            }
        }
        float* cs = g_cs[dir] + ((size_t)(b * NCH + chk) * C_ + c) * 8;
        #pragma unroll
        for (int n = 0; n < 4; n++) { cs[n * 2] = aP[n]; cs[n * 2 + 1] = h[n]; }
    }
}

// ---------------- K4: scan phase 2 ---------------------------------------------
__global__ void scan2_kernel() {
    int tg = blockIdx.x * 256 + threadIdx.x;
    int bd = tg >> 10;
    int cn = tg & 1023;
    int b = bd >> 1, dir = bd & 1;
    const float2* cs = (const float2*)(g_cs[dir] + (size_t)b * NCH * C_ * 8) + cn;
    float* h0 = g_h0[dir] + (size_t)b * NCH * C_ * 4 + cn;
    float B = 0.f;
    #pragma unroll 8
    for (int ch = 0; ch < NCH; ch++) {
        float2 v = cs[(size_t)ch * 1024];
        h0[(size_t)ch * 1024] = B;
        B = fmaf(v.x, B, v.y);
    }
}

// ---------------- K5: fused replay(f+b) + combine + silu(z) + LN ----------------
__global__ void scan3_fused_kernel(
    const float* __restrict__ Alog0, const float* __restrict__ Alog1,
    const float* __restrict__ D0, const float* __restrict__ D1,
    const float* __restrict__ nw, const float* __restrict__ nb) {
    __shared__ float sbcf[CHK * 8], sbcb[CHK * 8];
    __shared__ float ysm[CHK * C_];
    __shared__ float smu[CHK], srs[CHK];

    int ch = blockIdx.x;
    int b  = blockIdx.y;
    int c  = threadIdx.x;
    int chb = NCH - 1 - ch;
    int l0 = ch * CHK;

    {
        const float* gf = g_bc[0] + (size_t)(b * L_ + ch * CHK) * 8;
        const float* gb = g_bc[1] + (size_t)(b * L_ + chb * CHK) * 8;
        if (c < CHK * 8) { sbcf[c] = gf[c]; sbcb[c] = gb[c]; }
    }
    __syncthreads();

    // forward replay
    {
        float Av[4];
        #pragma unroll
        for (int n = 0; n < 4; n++) Av[n] = -__expf(Alog0[c * 4 + n]);
        float Dv = D0[c];
        const float* h0p = g_h0[0] + ((size_t)(b * NCH + ch) * C_ + c) * 4;
        float h[4];
        #pragma unroll
        for (int n = 0; n < 4; n++) h[n] = h0p[n];
        const __half2* dtu = &g_dtu[0][(size_t)(b * L_ + l0) * C_ + c];
        #pragma unroll 4
        for (int t = 0; t < CHK; t++) {
            float2 v = __half22float2(dtu[(size_t)t * C_]);
            float du = v.x * v.y;
            float y = v.y * Dv;
            #pragma unroll
            for (int n = 0; n < 4; n++) {
                float a = __expf(v.x * Av[n]);
                h[n] = fmaf(a, h[n], du * sbcf[t * 8 + n]);
                y = fmaf(h[n], sbcf[t * 8 + 4 + n], y);
            }
            ysm[t * C_ + c] = y;
        }
    }
    // backward replay
    {
        float Av[4];
        #pragma unroll
        for (int n = 0; n < 4; n++) Av[n] = -__expf(Alog1[c * 4 + n]);
        float Dv = D1[c];
        const float* h0p = g_h0[1] + ((size_t)(b * NCH + chb) * C_ + c) * 4;
        float h[4];
        #pragma unroll
        for (int n = 0; n < 4; n++) h[n] = h0p[n];
        const __half2* dtu = &g_dtu[1][(size_t)(b * L_ + chb * CHK) * C_ + c];
        #pragma unroll 4
        for (int tb = 0; tb < CHK; tb++) {
            float2 v = __half22float2(dtu[(size_t)tb * C_]);
            float du = v.x * v.y;
            float y = v.y * Dv;
            #pragma unroll
            for (int n = 0; n < 4; n++) {
                float a = __expf(v.x * Av[n]);
                h[n] = fmaf(a, h[n], du * sbcb[tb * 8 + n]);
                y = fmaf(h[n], sbcb[tb * 8 + 4 + n], y);
            }
            ysm[(CHK - 1 - tb) * C_ + c] += y;
        }
    }
    // z-gate
    {
        const float* zp = &g_z[(size_t)(b * L_ + l0) * C_ + c];
        #pragma unroll 4
        for (int t = 0; t < CHK; t++) {
            float z = zp[(size_t)t * C_];
            ysm[t * C_ + c] = 0.5f * ysm[t * C_ + c] * siluf(z);
        }
    }
    __syncthreads();
    // LN stats
    {
        int w = c >> 5, ln = c & 31;
        #pragma unroll
        for (int j = 0; j < 4; j++) {
            int t = w * 4 + j;
            float sm = 0.f, sq = 0.f;
            #pragma unroll
            for (int i = 0; i < 8; i++) {
                float v = ysm[t * C_ + ln + 32 * i];
                sm += v; sq += v * v;
            }
            #pragma unroll
            for (int o = 16; o; o >>= 1) {
                sm += __shfl_down_sync(0xffffffffu, sm, o);
                sq += __shfl_down_sync(0xffffffffu, sq, o);
            }
            if (ln == 0) {
                float mu = sm * (1.f / C_);
                float var = sq * (1.f / C_) - mu * mu;
                smu[t] = mu; srs[t] = rsqrtf(var + 1e-5f);
            }
        }
    }
    __syncthreads();
    {
        float wv = nw[c], bv = nb[c];
        #pragma unroll 4
        for (int t = 0; t < CHK; t++) {
            float v = (ysm[t * C_ + c] - smu[t]) * srs[t] * wv + bv;
            __nv_bfloat16 hh = __float2bfloat16(v);
            size_t o = (size_t)(b * L_ + l0 + t) * C_ + c;
            g_ah[o] = hh;
            g_al[o] = __float2bfloat16(v - __bfloat162float(hh));
        }
    }
}

// ---------------- launch ---------------------------------------------------------
extern "C" void kernel_launch(void* const* d_in, const int* in_sizes, int n_in,
                              void* d_out, int out_size) {
    const float* x        = (const float*)d_in[0];
    const float* ln_w     = (const float*)d_in[1];
    const float* ln_b     = (const float*)d_in[2];
    const float* in_proj  = (const float*)d_in[3];
    const float* cw_f     = (const float*)d_in[4];
    const float* cb_f     = (const float*)d_in[5];
    const float* xp_f     = (const float*)d_in[6];
    const float* dw_f     = (const float*)d_in[7];
    const float* db_f     = (const float*)d_in[8];
    const float* Alog_f   = (const float*)d_in[9];
    const float* D_f      = (const float*)d_in[10];
    const float* cw_b     = (const float*)d_in[11];
    const float* cb_b     = (const float*)d_in[12];
    const float* xp_b     = (const float*)d_in[13];
    const float* dw_b     = (const float*)d_in[14];
    const float* db_b     = (const float*)d_in[15];
    const float* Alog_b   = (const float*)d_in[16];
    const float* D_b      = (const float*)d_in[17];
    const float* nrm_w    = (const float*)d_in[18];
    const float* nrm_b    = (const float*)d_in[19];
    const float* out_proj = (const float*)d_in[20];
    float* out = (float*)d_out;

    float* gu;  cudaGetSymbolAddress((void**)&gu,  g_u);
    float* gz;  cudaGetSymbolAddress((void**)&gz,  g_z);
    __nv_bfloat16 *gah, *gal, *wih, *wil, *woh, *wol;
    cudaGetSymbolAddress((void**)&gah, g_ah);
    cudaGetSymbolAddress((void**)&gal, g_al);
    cudaGetSymbolAddress((void**)&wih, g_wih);
    cudaGetSymbolAddress((void**)&wil, g_wil);
    cudaGetSymbolAddress((void**)&woh, g_woh);
    cudaGetSymbolAddress((void**)&wol, g_wol);

    const int gemm_smem = 2 * BUF_BYTES;   // 147456 B
    cudaFuncSetAttribute(gemm_hmma, cudaFuncAttributeMaxDynamicSharedMemorySize, gemm_smem);
    const int conv_smem = (32 * C_ + 24 * C_ + 16 * C_ + 32 * 24) * 4;   // 76800 B
    cudaFuncSetAttribute(convscan_kernel, cudaFuncAttributeMaxDynamicSharedMemorySize, conv_smem);

    wprep_kernel<<<768, 256>>>(in_proj, out_proj);
    ln_kernel<<<BN_ * 128, 256>>>(x, ln_w, ln_b);
    gemm_hmma<<<dim3(4, BL_ / 128), 256, gemm_smem>>>(gah, gal, wih, wil, gu, gz, nullptr, 0);
    convscan_kernel<<<dim3(NCH, BN_ * 2), 256, conv_smem>>>(
        cw_f, cb_f, xp_f, dw_f, db_f, Alog_f,
        cw_b, cb_b, xp_b, dw_b, db_b, Alog_b);
    scan2_kernel<<<64, 256>>>();
    scan3_fused_kernel<<<dim3(NCH, BN_), 256>>>(Alog_f, Alog_b, D_f, D_b, nrm_w, nrm_b);
    gemm_hmma<<<dim3(2, BL_ / 128), 256, gemm_smem>>>(gah, gal, woh, wol, out, nullptr, x, 1);
}

// round 16
// speedup vs baseline: 1.1424x; 1.0090x over previous
#include <cuda_runtime.h>
#include <cuda_bf16.h>
#include <cuda_fp16.h>
#include <math.h>
#include <stdint.h>

#define BN_ 8
#define C_ 256
#define L_ 4096
#define BL_ (BN_*L_)
#define NCH 128
#define CHK 32
#define POS 32

// ---------------- scratch (device globals) -----------------------------------
__device__ __nv_bfloat16 g_ah[BL_*C_], g_al[BL_*C_];  // activation hi/lo
__device__ float   g_u  [BL_*C_];
__device__ float   g_z  [BL_*C_];
__device__ __half2 g_dtu[2][(size_t)BL_*C_];
__device__ float   g_bc [2][BL_*8];
__device__ float   g_cs [2][BN_*NCH*C_*8];
__device__ float   g_h0 [2][BN_*NCH*C_*4];
__device__ __nv_bfloat16 g_wih[512*256], g_wil[512*256];
__device__ __nv_bfloat16 g_woh[256*256], g_wol[256*256];

// ---------------- helpers -----------------------------------------------------
__device__ __forceinline__ float siluf(float x) { return x / (1.f + __expf(-x)); }

__device__ __forceinline__ uint32_t smem_u32(const void* p) {
    uint32_t a;
    asm("{ .reg .u64 t; cvta.to.shared.u64 t, %1; cvt.u32.u64 %0, t; }" : "=r"(a) : "l"(p));
    return a;
}

__device__ __forceinline__ void mma16816(float* c, const uint32_t* a, const uint32_t* b) {
    asm volatile(
        "mma.sync.aligned.m16n8k16.row.col.f32.bf16.bf16.f32 "
        "{%0,%1,%2,%3}, {%4,%5,%6,%7}, {%8,%9}, {%0,%1,%2,%3};"
        : "+f"(c[0]), "+f"(c[1]), "+f"(c[2]), "+f"(c[3])
        : "r"(a[0]), "r"(a[1]), "r"(a[2]), "r"(a[3]), "r"(b[0]), "r"(b[1]));
}

__device__ __forceinline__ void ldsm4(uint32_t* r, uint32_t addr) {
    asm volatile("ldmatrix.sync.aligned.m8n8.x4.shared.b16 {%0,%1,%2,%3}, [%4];"
        : "=r"(r[0]), "=r"(r[1]), "=r"(r[2]), "=r"(r[3]) : "r"(addr));
}

__device__ __forceinline__ void cpa16(uint32_t dst, const void* src) {
    asm volatile("cp.async.ca.shared.global [%0], [%1], 16;" :: "r"(dst), "l"(src));
}

__device__ __forceinline__ float dot4(float4 a, float4 b) {
    return fmaf(a.x, b.x, fmaf(a.y, b.y, fmaf(a.z, b.z, a.w * b.w)));
}

// ---------------- K0: weight pre-split ------------------------------------------
__global__ void wprep_kernel(const float* __restrict__ Wi, const float* __restrict__ Wo) {
    int i = blockIdx.x * 256 + threadIdx.x;
    if (i < 512 * 256) {
        float v = Wi[i];
        __nv_bfloat16 h = __float2bfloat16(v);
        g_wih[i] = h;
        g_wil[i] = __float2bfloat16(v - __bfloat162float(h));
    } else {
        int j = i - 512 * 256;
        float v = Wo[j];
        __nv_bfloat16 h = __float2bfloat16(v);
        g_woh[j] = h;
        g_wol[j] = __float2bfloat16(v - __bfloat162float(h));
    }
}

// ---------------- K1: tiled transpose + LayerNorm -> bf16 hi/lo ----------------
__global__ void ln_kernel(const float* __restrict__ x,
                          const float* __restrict__ wgt,
                          const float* __restrict__ bia) {
    __shared__ float s[C_][33];
    __shared__ float smu[32], srs[32];
    int b = blockIdx.x >> 7;
    int l0 = (blockIdx.x & 127) * 32;
    int tid = threadIdx.x, w = tid >> 5, ln = tid & 31;

    for (int c = w; c < C_; c += 8)
        s[c][ln] = x[((size_t)b * C_ + c) * L_ + l0 + ln];
    __syncthreads();

    #pragma unroll
    for (int j = 0; j < 4; j++) {
        int l = w * 4 + j;
        float sm = 0.f, sq = 0.f;
        #pragma unroll
        for (int i = 0; i < 8; i++) {
            float v = s[ln + 32 * i][l];
            sm += v; sq += v * v;
        }
        #pragma unroll
        for (int o = 16; o; o >>= 1) {
            sm += __shfl_down_sync(0xffffffffu, sm, o);
            sq += __shfl_down_sync(0xffffffffu, sq, o);
        }
        if (ln == 0) {
            float mu = sm * (1.f / C_);
            float var = sq * (1.f / C_) - mu * mu;
            smu[l] = mu; srs[l] = rsqrtf(var + 1e-5f);
        }
    }
    __syncthreads();

    int c = tid;
    float wv = wgt[c], bv = bia[c];
    for (int l = 0; l < 32; l++) {
        float v = (s[c][l] - smu[l]) * srs[l] * wv + bv;
        __nv_bfloat16 h = __float2bfloat16(v);
        size_t o = ((size_t)b * L_ + l0 + l) * C_ + c;
        g_ah[o] = h;
        g_al[o] = __float2bfloat16(v - __bfloat162float(h));
    }
}

// ---------------- K2: double-buffered cp.async split-bf16 HMMA GEMM ------------
// Staged epilogue: coalesced contiguous-row gmem writes in both modes.
#define SR 72
#define TILE_ELEM (128 * SR)
#define BUF_BYTES (4 * TILE_ELEM * 2)      // 73728
#define SST 132
__global__ void __launch_bounds__(256, 1) gemm_hmma(
    const __nv_bfloat16* __restrict__ Ah, const __nv_bfloat16* __restrict__ Al,
    const __nv_bfloat16* __restrict__ Wh, const __nv_bfloat16* __restrict__ Wl,
    float* __restrict__ out0, float* __restrict__ out1,
    const float* __restrict__ xres, int mode) {
    extern __shared__ __nv_bfloat16 sm[];
    uint32_t sbase = smem_u32(sm);

    int tid = threadIdx.x, wid = tid >> 5, lid = tid & 31;
    int g = lid >> 2, t = lid & 3;
    int warp_m = wid & 1, warp_n = wid >> 1;
    int n0 = blockIdx.x * 128, m0 = blockIdx.y * 128;

    float acc[4][4][4] = {};

    int frow = tid >> 1;
    int fkh = (tid & 1) * 32;
    const __nv_bfloat16* srcs[4];
    srcs[0] = Ah + (size_t)(m0 + frow) * 256 + fkh;
    srcs[1] = Al + (size_t)(m0 + frow) * 256 + fkh;
    srcs[2] = Wh + (size_t)(n0 + frow) * 256 + fkh;
    srcs[3] = Wl + (size_t)(n0 + frow) * 256 + fkh;
    uint32_t fill_dst = sbase + (frow * SR + fkh) * 2;

    uint32_t aoff = ((warp_m * 64 + (lid & 15)) * SR + (lid >> 4) * 8) * 2;
    int bn = (lid & 7) + ((lid >> 4) << 3);
    uint32_t boff = ((warp_n * 32 + bn) * SR + ((lid >> 3) & 1) * 8) * 2;

    #pragma unroll
    for (int p = 0; p < 2; p++) {
        uint32_t db = fill_dst + p * BUF_BYTES;
        #pragma unroll
        for (int tno = 0; tno < 4; tno++)
            #pragma unroll
            for (int j = 0; j < 4; j++)
                cpa16(db + tno * (TILE_ELEM * 2) + j * 16, srcs[tno] + p * 64 + j * 8);
        asm volatile("cp.async.commit_group;" ::: "memory");
    }

    #pragma unroll
    for (int kc = 0; kc < 4; kc++) {
        if (kc < 3) asm volatile("cp.async.wait_group 1;" ::: "memory");
        else        asm volatile("cp.async.wait_group 0;" ::: "memory");
        __syncthreads();

        uint32_t bb = sbase + (kc & 1) * BUF_BYTES;
        uint32_t sAh_b = bb, sAl_b = bb + TILE_ELEM * 2;
        uint32_t sBh_b = bb + TILE_ELEM * 4, sBl_b = bb + TILE_ELEM * 6;

        #pragma unroll
        for (int ks = 0; ks < 4; ks++) {
            uint32_t bh[2][4], bl[2][4];
            ldsm4(bh[0], sBh_b + boff + ks * 32);
            ldsm4(bh[1], sBh_b + boff + 16 * SR * 2 + ks * 32);
            ldsm4(bl[0], sBl_b + boff + ks * 32);
            ldsm4(bl[1], sBl_b + boff + 16 * SR * 2 + ks * 32);
            #pragma unroll
            for (int mi = 0; mi < 4; mi++) {
                uint32_t ah[4], al[4];
                ldsm4(ah, sAh_b + aoff + mi * 16 * SR * 2 + ks * 32);
                ldsm4(al, sAl_b + aoff + mi * 16 * SR * 2 + ks * 32);
                #pragma unroll
                for (int ni = 0; ni < 4; ni++) {
                    const uint32_t* bph = &bh[ni >> 1][(ni & 1) * 2];
                    const uint32_t* bpl = &bl[ni >> 1][(ni & 1) * 2];
                    mma16816(acc[mi][ni], ah, bph);
                    mma16816(acc[mi][ni], ah, bpl);
                    mma16816(acc[mi][ni], al, bph);
                }
            }
        }
        __syncthreads();
        if (kc < 2) {
            uint32_t db = fill_dst + (kc & 1) * BUF_BYTES;
            #pragma unroll
            for (int tno = 0; tno < 4; tno++)
                #pragma unroll
                for (int j = 0; j < 4; j++)
                    cpa16(db + tno * (TILE_ELEM * 2) + j * 16, srcs[tno] + (kc + 2) * 64 + j * 8);
            asm volatile("cp.async.commit_group;" ::: "memory");
        }
    }

    // -------- staged epilogue: scatter to smem, contiguous-row copy to gmem -----
    float* stage = (float*)sm;
    if (mode == 0) {
        // stage[m][n]
        #pragma unroll
        for (int mi = 0; mi < 4; mi++) {
            int r = warp_m * 64 + mi * 16 + g;
            #pragma unroll
            for (int ni = 0; ni < 4; ni++) {
                int n = warp_n * 32 + ni * 8 + t * 2;
                stage[r * SST + n]           = acc[mi][ni][0];
                stage[r * SST + n + 1]       = acc[mi][ni][1];
                stage[(r + 8) * SST + n]     = acc[mi][ni][2];
                stage[(r + 8) * SST + n + 1] = acc[mi][ni][3];
            }
        }
        __syncthreads();
        float* dst = (n0 < 256) ? out0 : out1;
        int nb = n0 & 255;
        // warp reads contiguous 128-float rows (conflict-free by phases),
        // writes coalesced 512B gmem rows
        #pragma unroll
        for (int i = 0; i < 16; i++) {
            int rr = wid * 16 + i;
            float4 v = *(const float4*)&stage[rr * SST + lid * 4];
            *(float4*)&dst[(size_t)(m0 + rr) * 256 + nb + lid * 4] = v;
        }
    } else {
        // stage transposed: stage[ch][l]
        #pragma unroll
        for (int mi = 0; mi < 4; mi++) {
            int r = warp_m * 64 + mi * 16 + g;
            #pragma unroll
            for (int ni = 0; ni < 4; ni++) {
                int n = warp_n * 32 + ni * 8 + t * 2;
                stage[n * SST + r]           = acc[mi][ni][0];
                stage[(n + 1) * SST + r]     = acc[mi][ni][1];
                stage[n * SST + r + 8]       = acc[mi][ni][2];
                stage[(n + 1) * SST + r + 8] = acc[mi][ni][3];
            }
        }
        __syncthreads();
        int bb2 = m0 >> 12, l0 = m0 & 4095;
        #pragma unroll
        for (int i = 0; i < 16; i++) {
            int chl = wid * 16 + i;
            float4 v = *(const float4*)&stage[chl * SST + lid * 4];
            size_t o = ((size_t)bb2 * C_ + n0 + chl) * L_ + l0 + lid * 4;
            float4 xr = *(const float4*)&xres[o];
            v.x += xr.x; v.y += xr.y; v.z += xr.z; v.w += xr.w;
            *(float4*)&out0[o] = v;
        }
    }
}

// ---------------- K3: conv + silu + x_proj + dt_proj + scan-phase1 -------------
__global__ void __launch_bounds__(256, 3) convscan_kernel(
    const float* __restrict__ cw0, const float* __restrict__ cb0,
    const float* __restrict__ xp0, const float* __restrict__ dw0, const float* __restrict__ db0,
    const float* __restrict__ Alog0,
    const float* __restrict__ cw1, const float* __restrict__ cb1,
    const float* __restrict__ xp1, const float* __restrict__ dw1, const float* __restrict__ db1,
    const float* __restrict__ Alog1) {
    extern __shared__ float sh[];
    float* sxc  = sh;                  // 32 x 256
    float* sxp  = sxc + 32 * C_;       // 24 x 256
    float* sdw4 = sxp + 24 * C_;       // [q][c] float4-contiguous
    float* sdbl = sdw4 + 16 * C_;      // 32 x 24

    int chk = blockIdx.x;
    int b = blockIdx.y >> 1, dir = blockIdx.y & 1;
    const float* cw = dir ? cw1 : cw0;
    const float* cb = dir ? cb1 : cb0;
    const float* xp = dir ? xp1 : xp0;
    const float* dw = dir ? dw1 : dw0;
    const float* db = dir ? db1 : db0;
    const float* Alog = dir ? Alog1 : Alog0;
    int tid = threadIdx.x;
    int q0 = chk * POS;

    for (int i = tid; i < 24 * C_; i += 256) sxp[i] = xp[i];
    for (int i = tid; i < 16 * C_; i += 256) {
        int c = i >> 4, r = i & 15;
        sdw4[(r >> 2) * 1024 + c * 4 + (r & 3)] = dw[i];
    }

    {   // conv + silu: rolling 4-register window over g_u
        int c = tid;
        float w0 = cw[c], w1 = cw[C_ + c], w2 = cw[2 * C_ + c], w3 = cw[3 * C_ + c];
        float cbv = cb[c];
        float u0 = 0.f, u1 = 0.f, u2 = 0.f;
        #pragma unroll
        for (int j = 0; j < 3; j++) {
            int q = q0 - 3 + j;
            float v = 0.f;
            if (q >= 0) {
                int phys = dir ? (L_ - 1 - q) : q;
                v = g_u[(size_t)(b * L_ + phys) * C_ + c];
            }
            if (j == 0) u0 = v; else if (j == 1) u1 = v; else u2 = v;
        }
        #pragma unroll 4
        for (int tp = 0; tp < POS; tp++) {
            int q = q0 + tp;
            int phys = dir ? (L_ - 1 - q) : q;
            float u3 = g_u[(size_t)(b * L_ + phys) * C_ + c];
            float acc = cbv;
            acc = fmaf(w0, u0, acc);
            acc = fmaf(w1, u1, acc);
            acc = fmaf(w2, u2, acc);
            acc = fmaf(w3, u3, acc);
            sxc[tp * C_ + c] = siluf(acc);
            u0 = u1; u1 = u2; u2 = u3;
        }
    }
    __syncthreads();

    {   // x_dbl: warp w owns outputs {3w,3w+1,3w+2}; its sxp rows in registers
        int w = tid >> 5, ln = tid & 31;
        int kq0 = 4 * ln, kq1 = 128 + 4 * ln;
        float4 pa0 = *(const float4*)&sxp[(w * 3 + 0) * C_ + kq0];
        float4 pb0 = *(const float4*)&sxp[(w * 3 + 0) * C_ + kq1];
        float4 pa1 = *(const float4*)&sxp[(w * 3 + 1) * C_ + kq0];
        float4 pb1 = *(const float4*)&sxp[(w * 3 + 1) * C_ + kq1];
        float4 pa2 = *(const float4*)&sxp[(w * 3 + 2) * C_ + kq0];
        float4 pb2 = *(const float4*)&sxp[(w * 3 + 2) * C_ + kq1];
        #pragma unroll 2
        for (int tp = 0; tp < POS; tp++) {
            float4 xa = *(const float4*)&sxc[tp * C_ + kq0];
            float4 xb = *(const float4*)&sxc[tp * C_ + kq1];
            float a0 = dot4(xa, pa0) + dot4(xb, pb0);
            float a1 = dot4(xa, pa1) + dot4(xb, pb1);
            float a2 = dot4(xa, pa2) + dot4(xb, pb2);
            #pragma unroll
            for (int of = 16; of; of >>= 1) {
                a0 += __shfl_down_sync(0xffffffffu, a0, of);
                a1 += __shfl_down_sync(0xffffffffu, a1, of);
                a2 += __shfl_down_sync(0xffffffffu, a2, of);
            }
            if (ln == 0) {
                sdbl[tp * 24 + w * 3 + 0] = a0;
                sdbl[tp * 24 + w * 3 + 1] = a1;
                sdbl[tp * 24 + w * 3 + 2] = a2;
            }
        }
    }
    __syncthreads();

    if (tid < POS * 8) {
        int pos = tid >> 3, v = tid & 7;
        g_bc[dir][(size_t)(b * L_ + q0 + pos) * 8 + v] = sdbl[pos * 24 + 16 + v];
    }

    {   // dt_proj + softplus + chunk summary
        int c = tid;
        float dbv = db[c];
        float4 wq0 = *(const float4*)&sdw4[0 * 1024 + c * 4];
        float4 wq1 = *(const float4*)&sdw4[1 * 1024 + c * 4];
        float4 wq2 = *(const float4*)&sdw4[2 * 1024 + c * 4];
        float4 wq3 = *(const float4*)&sdw4[3 * 1024 + c * 4];
        float Av[4];
        #pragma unroll
        for (int n = 0; n < 4; n++) Av[n] = -__expf(Alog[c * 4 + n]);
        float h[4] = {0, 0, 0, 0}, aP[4] = {1, 1, 1, 1};
        #pragma unroll 1
        for (int pos = 0; pos < POS; pos++) {
            float4 d0 = *(const float4*)&sdbl[pos * 24];
            float4 d1 = *(const float4*)&sdbl[pos * 24 + 4];
            float4 d2 = *(const float4*)&sdbl[pos * 24 + 8];
            float4 d3 = *(const float4*)&sdbl[pos * 24 + 12];
            float4 bcv = *(const float4*)&sdbl[pos * 24 + 16];
            float val = dbv + dot4(d0, wq0) + dot4(d1, wq1) + dot4(d2, wq2) + dot4(d3, wq3);
            float dtv = (val > 20.f) ? val : log1pf(__expf(val));
            float uu = sxc[pos * C_ + c];
            __half2 p = __floats2half2_rn(dtv, uu);
            g_dtu[dir][(size_t)(b * L_ + q0 + pos) * C_ + c] = p;
            float2 q = __half22float2(p);
            float du = q.x * q.y;
            float bcb[4] = {bcv.x, bcv.y, bcv.z, bcv.w};
            #pragma unroll
            for (int n = 0; n < 4; n++) {
                float a = __expf(q.x * Av[n]);
                h[n] = fmaf(a, h[n], du * bcb[n]);
                aP[n] *= a;
            }
        }
        float* cs = g_cs[dir] + ((size_t)(b * NCH + chk) * C_ + c) * 8;
        #pragma unroll
        for (int n = 0; n < 4; n++) { cs[n * 2] = aP[n]; cs[n * 2 + 1] = h[n]; }
    }
}

// ---------------- K4: scan phase 2 ---------------------------------------------
__global__ void scan2_kernel() {
    int tg = blockIdx.x * 256 + threadIdx.x;
    int bd = tg >> 10;
    int cn = tg & 1023;
    int b = bd >> 1, dir = bd & 1;
    const float2* cs = (const float2*)(g_cs[dir] + (size_t)b * NCH * C_ * 8) + cn;
    float* h0 = g_h0[dir] + (size_t)b * NCH * C_ * 4 + cn;
    float B = 0.f;
    #pragma unroll 8
    for (int ch = 0; ch < NCH; ch++) {
        float2 v = cs[(size_t)ch * 1024];
        h0[(size_t)ch * 1024] = B;
        B = fmaf(v.x, B, v.y);
    }
}

// ---------------- K5: fused replay(f+b) + combine + silu(z) + LN ----------------
__global__ void scan3_fused_kernel(
    const float* __restrict__ Alog0, const float* __restrict__ Alog1,
    const float* __restrict__ D0, const float* __restrict__ D1,
    const float* __restrict__ nw, const float* __restrict__ nb) {
    __shared__ float sbcf[CHK * 8], sbcb[CHK * 8];
    __shared__ float ysm[CHK * C_];
    __shared__ float smu[CHK], srs[CHK];

    int ch = blockIdx.x;
    int b  = blockIdx.y;
    int c  = threadIdx.x;
    int chb = NCH - 1 - ch;
    int l0 = ch * CHK;

    {
        const float* gf = g_bc[0] + (size_t)(b * L_ + ch * CHK) * 8;
        const float* gb = g_bc[1] + (size_t)(b * L_ + chb * CHK) * 8;
        if (c < CHK * 8) { sbcf[c] = gf[c]; sbcb[c] = gb[c]; }
    }
    __syncthreads();

    // forward replay
    {
        float Av[4];
        #pragma unroll
        for (int n = 0; n < 4; n++) Av[n] = -__expf(Alog0[c * 4 + n]);
        float Dv = D0[c];
        const float* h0p = g_h0[0] + ((size_t)(b * NCH + ch) * C_ + c) * 4;
        float h[4];
        #pragma unroll
        for (int n = 0; n < 4; n++) h[n] = h0p[n];
        const __half2* dtu = &g_dtu[0][(size_t)(b * L_ + l0) * C_ + c];
        #pragma unroll 4
        for (int t = 0; t < CHK; t++) {
            float2 v = __half22float2(dtu[(size_t)t * C_]);
            float du = v.x * v.y;
            float y = v.y * Dv;
            #pragma unroll
            for (int n = 0; n < 4; n++) {
                float a = __expf(v.x * Av[n]);
                h[n] = fmaf(a, h[n], du * sbcf[t * 8 + n]);
                y = fmaf(h[n], sbcf[t * 8 + 4 + n], y);
            }
            ysm[t * C_ + c] = y;
        }
    }
    // backward replay
    {
        float Av[4];
        #pragma unroll
        for (int n = 0; n < 4; n++) Av[n] = -__expf(Alog1[c * 4 + n]);
        float Dv = D1[c];
        const float* h0p = g_h0[1] + ((size_t)(b * NCH + chb) * C_ + c) * 4;
        float h[4];
        #pragma unroll
        for (int n = 0; n < 4; n++) h[n] = h0p[n];
        const __half2* dtu = &g_dtu[1][(size_t)(b * L_ + chb * CHK) * C_ + c];
        #pragma unroll 4
        for (int tb = 0; tb < CHK; tb++) {
            float2 v = __half22float2(dtu[(size_t)tb * C_]);
            float du = v.x * v.y;
            float y = v.y * Dv;
            #pragma unroll
            for (int n = 0; n < 4; n++) {
                float a = __expf(v.x * Av[n]);
                h[n] = fmaf(a, h[n], du * sbcb[tb * 8 + n]);
                y = fmaf(h[n], sbcb[tb * 8 + 4 + n], y);
            }
            ysm[(CHK - 1 - tb) * C_ + c] += y;
        }
    }
    // z-gate
    {
        const float* zp = &g_z[(size_t)(b * L_ + l0) * C_ + c];
        #pragma unroll 4
        for (int t = 0; t < CHK; t++) {
            float z = zp[(size_t)t * C_];
            ysm[t * C_ + c] = 0.5f * ysm[t * C_ + c] * siluf(z);
        }
    }
    __syncthreads();
    // LN stats
    {
        int w = c >> 5, ln = c & 31;
        #pragma unroll
        for (int j = 0; j < 4; j++) {
            int t = w * 4 + j;
            float sm = 0.f, sq = 0.f;
            #pragma unroll
            for (int i = 0; i < 8; i++) {
                float v = ysm[t * C_ + ln + 32 * i];
                sm += v; sq += v * v;
            }
            #pragma unroll
            for (int o = 16; o; o >>= 1) {
                sm += __shfl_down_sync(0xffffffffu, sm, o);
                sq += __shfl_down_sync(0xffffffffu, sq, o);
            }
            if (ln == 0) {
                float mu = sm * (1.f / C_);
                float var = sq * (1.f / C_) - mu * mu;
                smu[t] = mu; srs[t] = rsqrtf(var + 1e-5f);
            }
        }
    }
    __syncthreads();
    {
        float wv = nw[c], bv = nb[c];
        #pragma unroll 4
        for (int t = 0; t < CHK; t++) {
            float v = (ysm[t * C_ + c] - smu[t]) * srs[t] * wv + bv;
            __nv_bfloat16 hh = __float2bfloat16(v);
            size_t o = (size_t)(b * L_ + l0 + t) * C_ + c;
            g_ah[o] = hh;
            g_al[o] = __float2bfloat16(v - __bfloat162float(hh));
        }
    }
}

// ---------------- launch ---------------------------------------------------------
extern "C" void kernel_launch(void* const* d_in, const int* in_sizes, int n_in,
                              void* d_out, int out_size) {
    const float* x        = (const float*)d_in[0];
    const float* ln_w     = (const float*)d_in[1];
    const float* ln_b     = (const float*)d_in[2];
    const float* in_proj  = (const float*)d_in[3];
    const float* cw_f     = (const float*)d_in[4];
    const float* cb_f     = (const float*)d_in[5];
    const float* xp_f     = (const float*)d_in[6];
    const float* dw_f     = (const float*)d_in[7];
    const float* db_f     = (const float*)d_in[8];
    const float* Alog_f   = (const float*)d_in[9];
    const float* D_f      = (const float*)d_in[10];
    const float* cw_b     = (const float*)d_in[11];
    const float* cb_b     = (const float*)d_in[12];
    const float* xp_b     = (const float*)d_in[13];
    const float* dw_b     = (const float*)d_in[14];
    const float* db_b     = (const float*)d_in[15];
    const float* Alog_b   = (const float*)d_in[16];
    const float* D_b      = (const float*)d_in[17];
    const float* nrm_w    = (const float*)d_in[18];
    const float* nrm_b    = (const float*)d_in[19];
    const float* out_proj = (const float*)d_in[20];
    float* out = (float*)d_out;

    float* gu;  cudaGetSymbolAddress((void**)&gu,  g_u);
    float* gz;  cudaGetSymbolAddress((void**)&gz,  g_z);
    __nv_bfloat16 *gah, *gal, *wih, *wil, *woh, *wol;
    cudaGetSymbolAddress((void**)&gah, g_ah);
    cudaGetSymbolAddress((void**)&gal, g_al);
    cudaGetSymbolAddress((void**)&wih, g_wih);
    cudaGetSymbolAddress((void**)&wil, g_wil);
    cudaGetSymbolAddress((void**)&woh, g_woh);
    cudaGetSymbolAddress((void**)&wol, g_wol);

    const int gemm_smem = 2 * BUF_BYTES;   // 147456 B
    cudaFuncSetAttribute(gemm_hmma, cudaFuncAttributeMaxDynamicSharedMemorySize, gemm_smem);
    const int conv_smem = (32 * C_ + 24 * C_ + 16 * C_ + 32 * 24) * 4;   // 76800 B
    cudaFuncSetAttribute(convscan_kernel, cudaFuncAttributeMaxDynamicSharedMemorySize, conv_smem);

    wprep_kernel<<<768, 256>>>(in_proj, out_proj);
    ln_kernel<<<BN_ * 128, 256>>>(x, ln_w, ln_b);
    gemm_hmma<<<dim3(4, BL_ / 128), 256, gemm_smem>>>(gah, gal, wih, wil, gu, gz, nullptr, 0);
    convscan_kernel<<<dim3(NCH, BN_ * 2), 256, conv_smem>>>(
        cw_f, cb_f, xp_f, dw_f, db_f, Alog_f,
        cw_b, cb_b, xp_b, dw_b, db_b, Alog_b);
    scan2_kernel<<<64, 256>>>();
    scan3_fused_kernel<<<dim3(NCH, BN_), 256>>>(Alog_f, Alog_b, D_f, D_b, nrm_w, nrm_b);
    gemm_hmma<<<dim3(2, BL_ / 128), 256, gemm_smem>>>(gah, gal, woh, wol, out, nullptr, x, 1);
}

// round 17
// speedup vs baseline: 1.1624x; 1.0175x over previous
#include <cuda_runtime.h>
#include <cuda_bf16.h>
#include <cuda_fp16.h>
#include <math.h>
#include <stdint.h>

#define BN_ 8
#define C_ 256
#define L_ 4096
#define BL_ (BN_*L_)
#define NCH 128
#define CHK 32
#define POS 32

// ---------------- scratch (device globals) -----------------------------------
__device__ __nv_bfloat16 g_ah[BL_*C_], g_al[BL_*C_];  // activation hi/lo
__device__ float   g_u  [BL_*C_];
__device__ float   g_z  [BL_*C_];
__device__ __half2 g_dtu[2][(size_t)BL_*C_];
__device__ float   g_bc [2][BL_*8];
__device__ float   g_cs [2][BN_*NCH*C_*8];
__device__ float   g_h0 [2][BN_*NCH*C_*4];
__device__ __nv_bfloat16 g_wih[512*256], g_wil[512*256];
__device__ __nv_bfloat16 g_woh[256*256], g_wol[256*256];
__device__ __nv_bfloat16 g_xph[2][32*256], g_xpl[2][32*256];  // x_proj padded hi/lo

// ---------------- helpers -----------------------------------------------------
__device__ __forceinline__ float siluf(float x) { return x / (1.f + __expf(-x)); }

__device__ __forceinline__ uint32_t smem_u32(const void* p) {
    uint32_t a;
    asm("{ .reg .u64 t; cvta.to.shared.u64 t, %1; cvt.u32.u64 %0, t; }" : "=r"(a) : "l"(p));
    return a;
}

__device__ __forceinline__ void mma16816(float* c, const uint32_t* a, const uint32_t* b) {
    asm volatile(
        "mma.sync.aligned.m16n8k16.row.col.f32.bf16.bf16.f32 "
        "{%0,%1,%2,%3}, {%4,%5,%6,%7}, {%8,%9}, {%0,%1,%2,%3};"
        : "+f"(c[0]), "+f"(c[1]), "+f"(c[2]), "+f"(c[3])
        : "r"(a[0]), "r"(a[1]), "r"(a[2]), "r"(a[3]), "r"(b[0]), "r"(b[1]));
}

__device__ __forceinline__ void ldsm4(uint32_t* r, uint32_t addr) {
    asm volatile("ldmatrix.sync.aligned.m8n8.x4.shared.b16 {%0,%1,%2,%3}, [%4];"
        : "=r"(r[0]), "=r"(r[1]), "=r"(r[2]), "=r"(r[3]) : "r"(addr));
}

__device__ __forceinline__ void cpa16(uint32_t dst, const void* src) {
    asm volatile("cp.async.ca.shared.global [%0], [%1], 16;" :: "r"(dst), "l"(src));
}

__device__ __forceinline__ float dot4(float4 a, float4 b) {
    return fmaf(a.x, b.x, fmaf(a.y, b.y, fmaf(a.z, b.z, a.w * b.w)));
}

// ---------------- K0a: weight pre-split ------------------------------------------
__global__ void wprep_kernel(const float* __restrict__ Wi, const float* __restrict__ Wo) {
    int i = blockIdx.x * 256 + threadIdx.x;
    if (i < 512 * 256) {
        float v = Wi[i];
        __nv_bfloat16 h = __float2bfloat16(v);
        g_wih[i] = h;
        g_wil[i] = __float2bfloat16(v - __bfloat162float(h));
    } else {
        int j = i - 512 * 256;
        float v = Wo[j];
        __nv_bfloat16 h = __float2bfloat16(v);
        g_woh[j] = h;
        g_wol[j] = __float2bfloat16(v - __bfloat162float(h));
    }
}

// ---------------- K0b: x_proj pre-split (pad 24 -> 32 rows with zeros) -----------
__global__ void xprep_kernel(const float* __restrict__ xp0, const float* __restrict__ xp1) {
    int i = blockIdx.x * 256 + threadIdx.x;        // 64 blocks -> 16384
    int d = i >> 13, rc = i & 8191;
    int r = rc >> 8, c = rc & 255;
    const float* xp = d ? xp1 : xp0;
    float v = (r < 24) ? xp[r * 256 + c] : 0.f;
    __nv_bfloat16 h = __float2bfloat16(v);
    g_xph[d][rc] = h;
    g_xpl[d][rc] = __float2bfloat16(v - __bfloat162float(h));
}

// ---------------- K1: tiled transpose + LayerNorm -> bf16 hi/lo ----------------
__global__ void ln_kernel(const float* __restrict__ x,
                          const float* __restrict__ wgt,
                          const float* __restrict__ bia) {
    __shared__ float s[C_][33];
    __shared__ float smu[32], srs[32];
    int b = blockIdx.x >> 7;
    int l0 = (blockIdx.x & 127) * 32;
    int tid = threadIdx.x, w = tid >> 5, ln = tid & 31;

    for (int c = w; c < C_; c += 8)
        s[c][ln] = x[((size_t)b * C_ + c) * L_ + l0 + ln];
    __syncthreads();

    #pragma unroll
    for (int j = 0; j < 4; j++) {
        int l = w * 4 + j;
        float sm = 0.f, sq = 0.f;
        #pragma unroll
        for (int i = 0; i < 8; i++) {
            float v = s[ln + 32 * i][l];
            sm += v; sq += v * v;
        }
        #pragma unroll
        for (int o = 16; o; o >>= 1) {
            sm += __shfl_down_sync(0xffffffffu, sm, o);
            sq += __shfl_down_sync(0xffffffffu, sq, o);
        }
        if (ln == 0) {
            float mu = sm * (1.f / C_);
            float var = sq * (1.f / C_) - mu * mu;
            smu[l] = mu; srs[l] = rsqrtf(var + 1e-5f);
        }
    }
    __syncthreads();

    int c = tid;
    float wv = wgt[c], bv = bia[c];
    for (int l = 0; l < 32; l++) {
        float v = (s[c][l] - smu[l]) * srs[l] * wv + bv;
        __nv_bfloat16 h = __float2bfloat16(v);
        size_t o = ((size_t)b * L_ + l0 + l) * C_ + c;
        g_ah[o] = h;
        g_al[o] = __float2bfloat16(v - __bfloat162float(h));
    }
}

// ---------------- K2: double-buffered cp.async split-bf16 HMMA GEMM ------------
#define SR 72
#define TILE_ELEM (128 * SR)
#define BUF_BYTES (4 * TILE_ELEM * 2)      // 73728
#define SST 132
__global__ void __launch_bounds__(256, 1) gemm_hmma(
    const __nv_bfloat16* __restrict__ Ah, const __nv_bfloat16* __restrict__ Al,
    const __nv_bfloat16* __restrict__ Wh, const __nv_bfloat16* __restrict__ Wl,
    float* __restrict__ out0, float* __restrict__ out1,
    const float* __restrict__ xres, int mode) {
    extern __shared__ __nv_bfloat16 sm[];
    uint32_t sbase = smem_u32(sm);

    int tid = threadIdx.x, wid = tid >> 5, lid = tid & 31;
    int g = lid >> 2, t = lid & 3;
    int warp_m = wid & 1, warp_n = wid >> 1;
    int n0 = blockIdx.x * 128, m0 = blockIdx.y * 128;

    float acc[4][4][4] = {};

    int frow = tid >> 1;
    int fkh = (tid & 1) * 32;
    const __nv_bfloat16* srcs[4];
    srcs[0] = Ah + (size_t)(m0 + frow) * 256 + fkh;
    srcs[1] = Al + (size_t)(m0 + frow) * 256 + fkh;
    srcs[2] = Wh + (size_t)(n0 + frow) * 256 + fkh;
    srcs[3] = Wl + (size_t)(n0 + frow) * 256 + fkh;
    uint32_t fill_dst = sbase + (frow * SR + fkh) * 2;

    uint32_t aoff = ((warp_m * 64 + (lid & 15)) * SR + (lid >> 4) * 8) * 2;
    int bn = (lid & 7) + ((lid >> 4) << 3);
    uint32_t boff = ((warp_n * 32 + bn) * SR + ((lid >> 3) & 1) * 8) * 2;

    #pragma unroll
    for (int p = 0; p < 2; p++) {
        uint32_t db = fill_dst + p * BUF_BYTES;
        #pragma unroll
        for (int tno = 0; tno < 4; tno++)
            #pragma unroll
            for (int j = 0; j < 4; j++)
                cpa16(db + tno * (TILE_ELEM * 2) + j * 16, srcs[tno] + p * 64 + j * 8);
        asm volatile("cp.async.commit_group;" ::: "memory");
    }

    #pragma unroll
    for (int kc = 0; kc < 4; kc++) {
        if (kc < 3) asm volatile("cp.async.wait_group 1;" ::: "memory");
        else        asm volatile("cp.async.wait_group 0;" ::: "memory");
        __syncthreads();

        uint32_t bb = sbase + (kc & 1) * BUF_BYTES;
        uint32_t sAh_b = bb, sAl_b = bb + TILE_ELEM * 2;
        uint32_t sBh_b = bb + TILE_ELEM * 4, sBl_b = bb + TILE_ELEM * 6;

        #pragma unroll
        for (int ks = 0; ks < 4; ks++) {
            uint32_t bh[2][4], bl[2][4];
            ldsm4(bh[0], sBh_b + boff + ks * 32);
            ldsm4(bh[1], sBh_b + boff + 16 * SR * 2 + ks * 32);
            ldsm4(bl[0], sBl_b + boff + ks * 32);
            ldsm4(bl[1], sBl_b + boff + 16 * SR * 2 + ks * 32);
            #pragma unroll
            for (int mi = 0; mi < 4; mi++) {
                uint32_t ah[4], al[4];
                ldsm4(ah, sAh_b + aoff + mi * 16 * SR * 2 + ks * 32);
                ldsm4(al, sAl_b + aoff + mi * 16 * SR * 2 + ks * 32);
                #pragma unroll
                for (int ni = 0; ni < 4; ni++) {
                    const uint32_t* bph = &bh[ni >> 1][(ni & 1) * 2];
                    const uint32_t* bpl = &bl[ni >> 1][(ni & 1) * 2];
                    mma16816(acc[mi][ni], ah, bph);
                    mma16816(acc[mi][ni], ah, bpl);
                    mma16816(acc[mi][ni], al, bph);
                }
            }
        }
        __syncthreads();
        if (kc < 2) {
            uint32_t db = fill_dst + (kc & 1) * BUF_BYTES;
            #pragma unroll
            for (int tno = 0; tno < 4; tno++)
                #pragma unroll
                for (int j = 0; j < 4; j++)
                    cpa16(db + tno * (TILE_ELEM * 2) + j * 16, srcs[tno] + (kc + 2) * 64 + j * 8);
            asm volatile("cp.async.commit_group;" ::: "memory");
        }
    }

    // staged epilogue
    float* stage = (float*)sm;
    if (mode == 0) {
        #pragma unroll
        for (int mi = 0; mi < 4; mi++) {
            int r = warp_m * 64 + mi * 16 + g;
            #pragma unroll
            for (int ni = 0; ni < 4; ni++) {
                int n = warp_n * 32 + ni * 8 + t * 2;
                stage[r * SST + n]           = acc[mi][ni][0];
                stage[r * SST + n + 1]       = acc[mi][ni][1];
                stage[(r + 8) * SST + n]     = acc[mi][ni][2];
                stage[(r + 8) * SST + n + 1] = acc[mi][ni][3];
            }
        }
        __syncthreads();
        float* dst = (n0 < 256) ? out0 : out1;
        int nb = n0 & 255;
        #pragma unroll
        for (int i = 0; i < 16; i++) {
            int rr = wid * 16 + i;
            float4 v = *(const float4*)&stage[rr * SST + lid * 4];
            *(float4*)&dst[(size_t)(m0 + rr) * 256 + nb + lid * 4] = v;
        }
    } else {
        #pragma unroll
        for (int mi = 0; mi < 4; mi++) {
            int r = warp_m * 64 + mi * 16 + g;
            #pragma unroll
            for (int ni = 0; ni < 4; ni++) {
                int n = warp_n * 32 + ni * 8 + t * 2;
                stage[n * SST + r]           = acc[mi][ni][0];
                stage[(n + 1) * SST + r]     = acc[mi][ni][1];
                stage[n * SST + r + 8]       = acc[mi][ni][2];
                stage[(n + 1) * SST + r + 8] = acc[mi][ni][3];
            }
        }
        __syncthreads();
        int bb2 = m0 >> 12, l0 = m0 & 4095;
        #pragma unroll
        for (int i = 0; i < 16; i++) {
            int chl = wid * 16 + i;
            float4 v = *(const float4*)&stage[chl * SST + lid * 4];
            size_t o = ((size_t)bb2 * C_ + n0 + chl) * L_ + l0 + lid * 4;
            float4 xr = *(const float4*)&xres[o];
            v.x += xr.x; v.y += xr.y; v.z += xr.z; v.w += xr.w;
            *(float4*)&out0[o] = v;
        }
    }
}

// ---------------- K3: conv + silu + HMMA x_proj + dt_proj + scan-phase1 ---------
#define SXS 264
__global__ void __launch_bounds__(256, 3) convscan_kernel(
    const float* __restrict__ cw0, const float* __restrict__ cb0,
    const float* __restrict__ dw0, const float* __restrict__ db0,
    const float* __restrict__ Alog0,
    const float* __restrict__ cw1, const float* __restrict__ cb1,
    const float* __restrict__ dw1, const float* __restrict__ db1,
    const float* __restrict__ Alog1) {
    extern __shared__ char shraw[];
    __nv_bfloat16* sxch = (__nv_bfloat16*)shraw;          // 32 x 264
    __nv_bfloat16* sxcl = sxch + 32 * SXS;                // 32 x 264
    __nv_bfloat16* sxph = sxcl + 32 * SXS;                // 32 x 264 (B hi)
    __nv_bfloat16* sxpl = sxph + 32 * SXS;                // 32 x 264 (B lo)
    float* spart = (float*)sxph;                          // overlay: 8 x 32 x 33 fp32
    float* sdw4  = (float*)sxph;                          // overlay (after reduce)
    float* sdbl  = (float*)(sxpl + 32 * SXS);             // 32 x 24

    int chk = blockIdx.x;
    int b = blockIdx.y >> 1, dir = blockIdx.y & 1;
    const float* cw = dir ? cw1 : cw0;
    const float* cb = dir ? cb1 : cb0;
    const float* dw = dir ? dw1 : dw0;
    const float* db = dir ? db1 : db0;
    const float* Alog = dir ? Alog1 : Alog0;
    int tid = threadIdx.x;
    int q0 = chk * POS;

    // stage x_proj hi/lo (u32 copies, gmem row 256 -> smem row 264)
    {
        const uint32_t* gxh = (const uint32_t*)g_xph[dir];
        const uint32_t* gxl = (const uint32_t*)g_xpl[dir];
        for (int i = tid; i < 4096; i += 256) {
            int r = i >> 7, cc = (i & 127) << 1;
            *(uint32_t*)&sxph[r * SXS + cc] = gxh[i];
            *(uint32_t*)&sxpl[r * SXS + cc] = gxl[i];
        }
    }

    {   // conv + silu -> bf16 hi/lo
        int c = tid;
        float w0 = cw[c], w1 = cw[C_ + c], w2 = cw[2 * C_ + c], w3 = cw[3 * C_ + c];
        float cbv = cb[c];
        float u0 = 0.f, u1 = 0.f, u2 = 0.f;
        #pragma unroll
        for (int j = 0; j < 3; j++) {
            int q = q0 - 3 + j;
            float v = 0.f;
            if (q >= 0) {
                int phys = dir ? (L_ - 1 - q) : q;
                v = g_u[(size_t)(b * L_ + phys) * C_ + c];
            }
            if (j == 0) u0 = v; else if (j == 1) u1 = v; else u2 = v;
        }
        #pragma unroll 4
        for (int tp = 0; tp < POS; tp++) {
            int q = q0 + tp;
            int phys = dir ? (L_ - 1 - q) : q;
            float u3 = g_u[(size_t)(b * L_ + phys) * C_ + c];
            float acct = cbv;
            acct = fmaf(w0, u0, acct);
            acct = fmaf(w1, u1, acct);
            acct = fmaf(w2, u2, acct);
            acct = fmaf(w3, u3, acct);
            float v = siluf(acct);
            __nv_bfloat16 hh = __float2bfloat16(v);
            sxch[tp * SXS + c] = hh;
            sxcl[tp * SXS + c] = __float2bfloat16(v - __bfloat162float(hh));
            u0 = u1; u1 = u2; u2 = u3;
        }
    }
    __syncthreads();

    {   // x_dbl mini-GEMM: warp w owns K slice [32w, 32w+32), 3-term split-bf16
        int w = tid >> 5, lid = tid & 31;
        uint32_t sxch_b = smem_u32(sxch), sxcl_b = smem_u32(sxcl);
        uint32_t sxph_b = smem_u32(sxph), sxpl_b = smem_u32(sxpl);
        int wK = w * 32;
        int bn = (lid & 7) + ((lid >> 4) << 3);
        float acc2[2][4][4] = {};
        #pragma unroll
        for (int mt = 0; mt < 2; mt++) {
            #pragma unroll
            for (int ks = 0; ks < 2; ks++) {
                int kb = wK + ks * 16;
                uint32_t a_off = ((((lid & 15) + mt * 16) * SXS) + kb + (lid >> 4) * 8) * 2;
                uint32_t ah[4], al[4];
                ldsm4(ah, sxch_b + a_off);
                ldsm4(al, sxcl_b + a_off);
                #pragma unroll
                for (int p = 0; p < 2; p++) {
                    uint32_t b_off = (((p * 16 + bn) * SXS) + kb + ((lid >> 3) & 1) * 8) * 2;
                    uint32_t bh4[4], bl4[4];
                    ldsm4(bh4, sxph_b + b_off);
                    ldsm4(bl4, sxpl_b + b_off);
                    #pragma unroll
                    for (int q = 0; q < 2; q++) {
                        int ni = p * 2 + q;
                        mma16816(acc2[mt][ni], ah, &bh4[q * 2]);
                        mma16816(acc2[mt][ni], ah, &bl4[q * 2]);
                        mma16816(acc2[mt][ni], al, &bh4[q * 2]);
                    }
                }
            }
        }
        __syncthreads();   // all B reads done before overlay
        float* pw = spart + w * 1056;
        int gg = lid >> 2, tt = lid & 3;
        #pragma unroll
        for (int mt = 0; mt < 2; mt++)
            #pragma unroll
            for (int ni = 0; ni < 4; ni++) {
                int colb = ni * 8 + tt * 2;
                pw[(mt * 16 + gg) * 33 + colb]         = acc2[mt][ni][0];
                pw[(mt * 16 + gg) * 33 + colb + 1]     = acc2[mt][ni][1];
                pw[(mt * 16 + gg + 8) * 33 + colb]     = acc2[mt][ni][2];
                pw[(mt * 16 + gg + 8) * 33 + colb + 1] = acc2[mt][ni][3];
            }
    }
    __syncthreads();

    {   // reduce 8 K-partials -> sdbl
        int pos = tid >> 3, j = tid & 7;
        #pragma unroll
        for (int jj = 0; jj < 3; jj++) {
            int o = j * 3 + jj;
            float s = 0.f;
            #pragma unroll
            for (int w2 = 0; w2 < 8; w2++)
                s += spart[w2 * 1056 + pos * 33 + o];
            sdbl[pos * 24 + o] = s;
        }
    }
    __syncthreads();

    // stage dt weights into overlay; write Bc/Cc
    for (int i = tid; i < 16 * C_; i += 256) {
        int c2 = i >> 4, r2 = i & 15;
        sdw4[(r2 >> 2) * 1024 + c2 * 4 + (r2 & 3)] = dw[i];
    }
    if (tid < POS * 8) {
        int pos = tid >> 3, v = tid & 7;
        g_bc[dir][(size_t)(b * L_ + q0 + pos) * 8 + v] = sdbl[pos * 24 + 16 + v];
    }
    __syncthreads();

    {   // dt_proj + softplus + chunk summary
        int c = tid;
        float dbv = db[c];
        float4 wq0 = *(const float4*)&sdw4[0 * 1024 + c * 4];
        float4 wq1 = *(const float4*)&sdw4[1 * 1024 + c * 4];
        float4 wq2 = *(const float4*)&sdw4[2 * 1024 + c * 4];
        float4 wq3 = *(const float4*)&sdw4[3 * 1024 + c * 4];
        float Av[4];
        #pragma unroll
        for (int n = 0; n < 4; n++) Av[n] = -__expf(Alog[c * 4 + n]);
        float h[4] = {0, 0, 0, 0}, aP[4] = {1, 1, 1, 1};
        #pragma unroll 1
        for (int pos = 0; pos < POS; pos++) {
            float4 d0 = *(const float4*)&sdbl[pos * 24];
            float4 d1 = *(const float4*)&sdbl[pos * 24 + 4];
            float4 d2 = *(const float4*)&sdbl[pos * 24 + 8];
            float4 d3 = *(const float4*)&sdbl[pos * 24 + 12];
            float4 bcv = *(const float4*)&sdbl[pos * 24 + 16];
            float val = dbv + dot4(d0, wq0) + dot4(d1, wq1) + dot4(d2, wq2) + dot4(d3, wq3);
            float dtv = (val > 20.f) ? val : log1pf(__expf(val));
            float uu = __bfloat162float(sxch[pos * SXS + c]) + __bfloat162float(sxcl[pos * SXS + c]);
            __half2 p = __floats2half2_rn(dtv, uu);
            g_dtu[dir][(size_t)(b * L_ + q0 + pos) * C_ + c] = p;
            float2 q = __half22float2(p);
            float du = q.x * q.y;
            float bcb[4] = {bcv.x, bcv.y, bcv.z, bcv.w};
            #pragma unroll
            for (int n = 0; n < 4; n++) {
                float a = __expf(q.x * Av[n]);
                h[n] = fmaf(a, h[n], du * bcb[n]);
                aP[n] *= a;
            }
        }
        float* cs = g_cs[dir] + ((size_t)(b * NCH + chk) * C_ + c) * 8;
        #pragma unroll
        for (int n = 0; n < 4; n++) { cs[n * 2] = aP[n]; cs[n * 2 + 1] = h[n]; }
    }
}

// ---------------- K4: scan phase 2 ---------------------------------------------
__global__ void scan2_kernel() {
    int tg = blockIdx.x * 256 + threadIdx.x;
    int bd = tg >> 10;
    int cn = tg & 1023;
    int b = bd >> 1, dir = bd & 1;
    const float2* cs = (const float2*)(g_cs[dir] + (size_t)b * NCH * C_ * 8) + cn;
    float* h0 = g_h0[dir] + (size_t)b * NCH * C_ * 4 + cn;
    float B = 0.f;
    #pragma unroll 8
    for (int ch = 0; ch < NCH; ch++) {
        float2 v = cs[(size_t)ch * 1024];
        h0[(size_t)ch * 1024] = B;
        B = fmaf(v.x, B, v.y);
    }
}

// ---------------- K5: fused replay(f+b) + combine + silu(z) + LN ----------------
__global__ void scan3_fused_kernel(
    const float* __restrict__ Alog0, const float* __restrict__ Alog1,
    const float* __restrict__ D0, const float* __restrict__ D1,
    const float* __restrict__ nw, const float* __restrict__ nb) {
    __shared__ float sbcf[CHK * 8], sbcb[CHK * 8];
    __shared__ float ysm[CHK * C_];
    __shared__ float smu[CHK], srs[CHK];

    int ch = blockIdx.x;
    int b  = blockIdx.y;
    int c  = threadIdx.x;
    int chb = NCH - 1 - ch;
    int l0 = ch * CHK;

    {
        const float* gf = g_bc[0] + (size_t)(b * L_ + ch * CHK) * 8;
        const float* gb = g_bc[1] + (size_t)(b * L_ + chb * CHK) * 8;
        if (c < CHK * 8) { sbcf[c] = gf[c]; sbcb[c] = gb[c]; }
    }
    __syncthreads();

    // forward replay
    {
        float Av[4];
        #pragma unroll
        for (int n = 0; n < 4; n++) Av[n] = -__expf(Alog0[c * 4 + n]);
        float Dv = D0[c];
        const float* h0p = g_h0[0] + ((size_t)(b * NCH + ch) * C_ + c) * 4;
        float h[4];
        #pragma unroll
        for (int n = 0; n < 4; n++) h[n] = h0p[n];
        const __half2* dtu = &g_dtu[0][(size_t)(b * L_ + l0) * C_ + c];
        #pragma unroll 4
        for (int t = 0; t < CHK; t++) {
            float2 v = __half22float2(dtu[(size_t)t * C_]);
            float du = v.x * v.y;
            float y = v.y * Dv;
            #pragma unroll
            for (int n = 0; n < 4; n++) {
                float a = __expf(v.x * Av[n]);
                h[n] = fmaf(a, h[n], du * sbcf[t * 8 + n]);
                y = fmaf(h[n], sbcf[t * 8 + 4 + n], y);
            }
            ysm[t * C_ + c] = y;
        }
    }
    // backward replay
    {
        float Av[4];
        #pragma unroll
        for (int n = 0; n < 4; n++) Av[n] = -__expf(Alog1[c * 4 + n]);
        float Dv = D1[c];
        const float* h0p = g_h0[1] + ((size_t)(b * NCH + chb) * C_ + c) * 4;
        float h[4];
        #pragma unroll
        for (int n = 0; n < 4; n++) h[n] = h0p[n];
        const __half2* dtu = &g_dtu[1][(size_t)(b * L_ + chb * CHK) * C_ + c];
        #pragma unroll 4
        for (int tb = 0; tb < CHK; tb++) {
            float2 v = __half22float2(dtu[(size_t)tb * C_]);
            float du = v.x * v.y;
            float y = v.y * Dv;
            #pragma unroll
            for (int n = 0; n < 4; n++) {
                float a = __expf(v.x * Av[n]);
                h[n] = fmaf(a, h[n], du * sbcb[tb * 8 + n]);
                y = fmaf(h[n], sbcb[tb * 8 + 4 + n], y);
            }
            ysm[(CHK - 1 - tb) * C_ + c] += y;
        }
    }
    // z-gate
    {
        const float* zp = &g_z[(size_t)(b * L_ + l0) * C_ + c];
        #pragma unroll 4
        for (int t = 0; t < CHK; t++) {
            float z = zp[(size_t)t * C_];
            ysm[t * C_ + c] = 0.5f * ysm[t * C_ + c] * siluf(z);
        }
    }
    __syncthreads();
    // LN stats
    {
        int w = c >> 5, ln = c & 31;
        #pragma unroll
        for (int j = 0; j < 4; j++) {
            int t = w * 4 + j;
            float sm = 0.f, sq = 0.f;
            #pragma unroll
            for (int i = 0; i < 8; i++) {
                float v = ysm[t * C_ + ln + 32 * i];
                sm += v; sq += v * v;
            }
            #pragma unroll
            for (int o = 16; o; o >>= 1) {
                sm += __shfl_down_sync(0xffffffffu, sm, o);
                sq += __shfl_down_sync(0xffffffffu, sq, o);
            }
            if (ln == 0) {
                float mu = sm * (1.f / C_);
                float var = sq * (1.f / C_) - mu * mu;
                smu[t] = mu; srs[t] = rsqrtf(var + 1e-5f);
            }
        }
    }
    __syncthreads();
    {
        float wv = nw[c], bv = nb[c];
        #pragma unroll 4
        for (int t = 0; t < CHK; t++) {
            float v = (ysm[t * C_ + c] - smu[t]) * srs[t] * wv + bv;
            __nv_bfloat16 hh = __float2bfloat16(v);
            size_t o = (size_t)(b * L_ + l0 + t) * C_ + c;
            g_ah[o] = hh;
            g_al[o] = __float2bfloat16(v - __bfloat162float(hh));
        }
    }
}

// ---------------- launch ---------------------------------------------------------
extern "C" void kernel_launch(void* const* d_in, const int* in_sizes, int n_in,
                              void* d_out, int out_size) {
    const float* x        = (const float*)d_in[0];
    const float* ln_w     = (const float*)d_in[1];
    const float* ln_b     = (const float*)d_in[2];
    const float* in_proj  = (const float*)d_in[3];
    const float* cw_f     = (const float*)d_in[4];
    const float* cb_f     = (const float*)d_in[5];
    const float* xp_f     = (const float*)d_in[6];
    const float* dw_f     = (const float*)d_in[7];
    const float* db_f     = (const float*)d_in[8];
    const float* Alog_f   = (const float*)d_in[9];
    const float* D_f      = (const float*)d_in[10];
    const float* cw_b     = (const float*)d_in[11];
    const float* cb_b     = (const float*)d_in[12];
    const float* xp_b     = (const float*)d_in[13];
    const float* dw_b     = (const float*)d_in[14];
    const float* db_b     = (const float*)d_in[15];
    const float* Alog_b   = (const float*)d_in[16];
    const float* D_b      = (const float*)d_in[17];
    const float* nrm_w    = (const float*)d_in[18];
    const float* nrm_b    = (const float*)d_in[19];
    const float* out_proj = (const float*)d_in[20];
    float* out = (float*)d_out;

    float* gu;  cudaGetSymbolAddress((void**)&gu,  g_u);
    float* gz;  cudaGetSymbolAddress((void**)&gz,  g_z);
    __nv_bfloat16 *gah, *gal, *wih, *wil, *woh, *wol;
    cudaGetSymbolAddress((void**)&gah, g_ah);
    cudaGetSymbolAddress((void**)&gal, g_al);
    cudaGetSymbolAddress((void**)&wih, g_wih);
    cudaGetSymbolAddress((void**)&wil, g_wil);
    cudaGetSymbolAddress((void**)&woh, g_woh);
    cudaGetSymbolAddress((void**)&wol, g_wol);

    const int gemm_smem = 2 * BUF_BYTES;                          // 147456 B
    cudaFuncSetAttribute(gemm_hmma, cudaFuncAttributeMaxDynamicSharedMemorySize, gemm_smem);
    const int conv_smem = 4 * 32 * SXS * 2 + 32 * 24 * 4;         // 70656 B
    cudaFuncSetAttribute(convscan_kernel, cudaFuncAttributeMaxDynamicSharedMemorySize, conv_smem);

    wprep_kernel<<<768, 256>>>(in_proj, out_proj);
    xprep_kernel<<<64, 256>>>(xp_f, xp_b);
    ln_kernel<<<BN_ * 128, 256>>>(x, ln_w, ln_b);
    gemm_hmma<<<dim3(4, BL_ / 128), 256, gemm_smem>>>(gah, gal, wih, wil, gu, gz, nullptr, 0);
    convscan_kernel<<<dim3(NCH, BN_ * 2), 256, conv_smem>>>(
        cw_f, cb_f, dw_f, db_f, Alog_f,
        cw_b, cb_b, dw_b, db_b, Alog_b);
    scan2_kernel<<<64, 256>>>();
    scan3_fused_kernel<<<dim3(NCH, BN_), 256>>>(Alog_f, Alog_b, D_f, D_b, nrm_w, nrm_b);
    gemm_hmma<<<dim3(2, BL_ / 128), 256, gemm_smem>>>(gah, gal, woh, wol, out, nullptr, x, 1);
}